// round 4
// baseline (speedup 1.0000x reference)
#include <cuda_runtime.h>
#include <cuda_bf16.h>
#include <float.h>
#include <stdint.h>

#define NMAX 4096
#define DIMK 256              // fp32 features per row
#define KC   64               // bf16 elements per K-chunk (128 bytes per row)
#define NCH  (DIMK / KC)      // 4 chunks per tile
#define NSTG 3                // smem pipeline stages

// ---------------- device scratch (no allocs allowed) ----------------
__device__ int   g_posmax[NMAX];                 // max d^2 over positives, float bits
__device__ int   g_negmin[NMAX];                 // min d^2 over negatives, float bits
__device__ float g_xx[NMAX];                     // squared norms
__device__ int   g_lab[NMAX];                    // normalized labels
__device__ __align__(16) __nv_bfloat16 g_hi[NMAX * DIMK];
__device__ __align__(16) __nv_bfloat16 g_lo[NMAX * DIMK];

// ---------------- baseline-ISA PTX helpers (sm_80+, no 'a' features) --------
__device__ __forceinline__ uint32_t s2u(const void* p) {
    uint32_t a;
    asm("{ .reg .u64 t; cvta.to.shared.u64 t, %1; cvt.u32.u64 %0, t; }" : "=r"(a) : "l"(p));
    return a;
}
__device__ __forceinline__ void cp16(uint32_t saddr, const void* g) {
    asm volatile("cp.async.cg.shared.global [%0], [%1], 16;" :: "r"(saddr), "l"(g) : "memory");
}
#define CP_COMMIT() asm volatile("cp.async.commit_group;" ::: "memory")
template <int N> __device__ __forceinline__ void cp_wait() {
    asm volatile("cp.async.wait_group %0;" :: "n"(N) : "memory");
}
__device__ __forceinline__ void ldsm4(uint32_t* r, uint32_t a) {
    asm volatile("ldmatrix.sync.aligned.m8n8.x4.shared.b16 {%0,%1,%2,%3}, [%4];"
                 : "=r"(r[0]), "=r"(r[1]), "=r"(r[2]), "=r"(r[3]) : "r"(a));
}
__device__ __forceinline__ void mma16816(float* d, const uint32_t* a, const uint32_t* b) {
    asm volatile(
        "mma.sync.aligned.m16n8k16.row.col.f32.bf16.bf16.f32 "
        "{%0,%1,%2,%3}, {%4,%5,%6,%7}, {%8,%9}, {%0,%1,%2,%3};"
        : "+f"(d[0]), "+f"(d[1]), "+f"(d[2]), "+f"(d[3])
        : "r"(a[0]), "r"(a[1]), "r"(a[2]), "r"(a[3]), "r"(b[0]), "r"(b[1]));
}
#define SWZ(x) ((x) ^ ((((uint32_t)(x)) >> 3) & 0x70))

// SMEM layout (relative to 128-aligned base)
#define SM_LABI  0            // 128 int
#define SM_XXI   512          // 128 float
#define SM_LABJ  1024
#define SM_XXJ   1536
#define SM_STAGE 2048         // NSTG stages x 64KB; 4 components of 16KB each
#define STAGE_SZ 65536
#define COMP_SZ  16384
#define SMEM_TOTAL (SM_STAGE + NSTG * STAGE_SZ + 128)

// ---------------------------------------------------------------------------
// Prep: bf16 hi/lo split, squared norms, label normalization, init.
// ---------------------------------------------------------------------------
__global__ void prep_kernel(const float* __restrict__ feat,
                            const int* __restrict__ lab_raw, int n) {
    int row  = blockIdx.x * 8 + (threadIdx.x >> 5);
    int lane = threadIdx.x & 31;
    if (row >= n) return;

    const float4* p = (const float4*)(feat + (size_t)row * DIMK);
    float4 v0 = p[lane];
    float4 v1 = p[lane + 32];

    float s = v0.x * v0.x + v0.y * v0.y + v0.z * v0.z + v0.w * v0.w
            + v1.x * v1.x + v1.y * v1.y + v1.z * v1.z + v1.w * v1.w;

    float4 vv[2] = {v0, v1};
#pragma unroll
    for (int i = 0; i < 2; i++) {
        float4 v = vv[i];
        __nv_bfloat16 hx = __float2bfloat16(v.x), hy = __float2bfloat16(v.y);
        __nv_bfloat16 hz = __float2bfloat16(v.z), hw = __float2bfloat16(v.w);
        int base = row * DIMK + (lane + 32 * i) * 4;
        __nv_bfloat162* H = (__nv_bfloat162*)(g_hi + base);
        __nv_bfloat162 h0; h0.x = hx; h0.y = hy;
        __nv_bfloat162 h1; h1.x = hz; h1.y = hw;
        H[0] = h0; H[1] = h1;
        __nv_bfloat162* L = (__nv_bfloat162*)(g_lo + base);
        __nv_bfloat162 l0, l1;
        l0.x = __float2bfloat16(v.x - __bfloat162float(hx));
        l0.y = __float2bfloat16(v.y - __bfloat162float(hy));
        l1.x = __float2bfloat16(v.z - __bfloat162float(hz));
        l1.y = __float2bfloat16(v.w - __bfloat162float(hw));
        L[0] = l0; L[1] = l1;
    }
#pragma unroll
    for (int o = 16; o; o >>= 1) s += __shfl_xor_sync(0xffffffffu, s, o);

    if (lane == 0) {
        g_xx[row]     = s;
        g_posmax[row] = 0;                       // bits of +0.0f
        g_negmin[row] = __float_as_int(FLT_MAX);
    }
    if (lane == 1) {
        bool is64 = true;
#pragma unroll
        for (int i = 0; i < 32; i++)
            if (lab_raw[2 * i + 1] != 0) { is64 = false; break; }
        g_lab[row] = is64 ? lab_raw[2 * row] : lab_raw[row];
    }
}

// ---------------------------------------------------------------------------
// Upper-triangle tile index -> (bi, bj)
// ---------------------------------------------------------------------------
__device__ __forceinline__ void decode_tile(int t, int ntb, int& bi, int& bj) {
    int ti = 0;
    while (t >= ntb - ti) { t -= ntb - ti; ti++; }
    bi = ti << 7;
    bj = (ti + t) << 7;
}

// ---------------------------------------------------------------------------
// Load one 64-wide K chunk (4 components x 128 rows x 128B, SW128 swizzled)
// ---------------------------------------------------------------------------
__device__ __forceinline__ void load_chunk(uint32_t stage, int bi, int bj,
                                           int c, int tid) {
    const int row  = tid & 127;
    const int half = tid >> 7;       // 0/1: which 64B half of the row
    const size_t ga = (size_t)(bi + row) * DIMK + c * KC;
    const size_t gb = (size_t)(bj + row) * DIMK + c * KC;
    const char* Ah = (const char*)(g_hi + ga);
    const char* Al = (const char*)(g_lo + ga);
    const char* Bh = (const char*)(g_hi + gb);
    const char* Bl = (const char*)(g_lo + gb);
    const uint32_t ro = (uint32_t)row * 128;
#pragma unroll
    for (int q = 0; q < 4; q++) {
        uint32_t off = half * 64 + q * 16;
        uint32_t so  = SWZ(ro + off);
        cp16(stage + 0 * COMP_SZ + so, Ah + off);
        cp16(stage + 1 * COMP_SZ + so, Al + off);
        cp16(stage + 2 * COMP_SZ + so, Bh + off);
        cp16(stage + 3 * COMP_SZ + so, Bl + off);
    }
}

// ---------------------------------------------------------------------------
// MMA over one chunk: acc += Ah*Bh^T + Ah*Bl^T + Al*Bh^T  (per-warp 32x64)
// ---------------------------------------------------------------------------
__device__ __forceinline__ void mma_chunk_w(float acc[2][8][4], uint32_t st,
                                            int m_base, int n_base, int lane) {
    const uint32_t sAh = st, sAl = st + COMP_SZ;
    const uint32_t sBh = st + 2 * COMP_SZ, sBl = st + 3 * COMP_SZ;
#pragma unroll
    for (int s = 0; s < 4; s++) {                 // k16 steps within KC=64
        const uint32_t koff = (uint32_t)s * 32 + ((lane >> 4) << 4);
        uint32_t ah[2][4], al[2][4], bh[4][4], bl[4][4];
#pragma unroll
        for (int mt = 0; mt < 2; mt++) {
            uint32_t ad = SWZ((uint32_t)(m_base + mt * 16 + (lane & 15)) * 128 + koff);
            ldsm4(ah[mt], sAh + ad);
            ldsm4(al[mt], sAl + ad);
        }
#pragma unroll
        for (int p = 0; p < 4; p++) {             // each x4 covers 2 n-tiles
            uint32_t bd = SWZ((uint32_t)(n_base + p * 16 + (lane & 15)) * 128 + koff);
            ldsm4(bh[p], sBh + bd);
            ldsm4(bl[p], sBl + bd);
        }
#pragma unroll
        for (int mt = 0; mt < 2; mt++)
#pragma unroll
            for (int nt = 0; nt < 8; nt++) {
                const int p = nt >> 1, q = nt & 1;
                uint32_t bH[2] = {bh[p][q], bh[p][2 + q]};
                uint32_t bL[2] = {bl[p][q], bl[p][2 + q]};
                mma16816(acc[mt][nt], ah[mt], bH);   // hi*hi
                mma16816(acc[mt][nt], ah[mt], bL);   // hi*lo
                mma16816(acc[mt][nt], al[mt], bH);   // lo*hi
            }
    }
}

// ---------------------------------------------------------------------------
// Persistent flat-stream kernel: 3-stage ring, cross-tile prefetch,
// one sync per chunk, dual-direction masked epilogue.
// ---------------------------------------------------------------------------
__global__ void __launch_bounds__(256, 1) tile_kernel(int n) {
    extern __shared__ char smem_raw[];
    uint32_t sb_raw = s2u(smem_raw);
    uint32_t pad = (128u - (sb_raw & 127u)) & 127u;
    char* sm = smem_raw + pad;
    uint32_t sb = sb_raw + pad;

    int*   labi = (int*)(sm + SM_LABI);
    float* xxi  = (float*)(sm + SM_XXI);
    int*   labj = (int*)(sm + SM_LABJ);
    float* xxj  = (float*)(sm + SM_XXJ);

    const int tid = threadIdx.x, lane = tid & 31, w = tid >> 5;
    const int m_base = (w & 3) * 32;     // 4 warps along M
    const int n_base = (w >> 2) * 64;    // 2 warps along N

    const int ntb = n >> 7;
    const int T   = ntb * (ntb + 1) / 2;          // upper triangle incl. diagonal
    const int myT = (T - (int)blockIdx.x + (int)gridDim.x - 1) / (int)gridDim.x;
    const int G   = myT * NCH;                    // chunks this CTA streams
    if (G == 0) return;

    // rolling tile coords for load-target and mma-target chunks
    int lbi, lbj;                                 // tile of the chunk being loaded
    int mbi = 0, mbj = 0;                         // tile of the chunk being MMA'd
    decode_tile(blockIdx.x, ntb, lbi, lbj);

    // prologue: chunks 0 and 1 (both belong to local tile 0)
    load_chunk(sb + SM_STAGE + 0 * STAGE_SZ, lbi, lbj, 0, tid);
    CP_COMMIT();
    load_chunk(sb + SM_STAGE + 1 * STAGE_SZ, lbi, lbj, 1, tid);
    CP_COMMIT();

    float acc[2][8][4];
    int stg = 0;                                  // stage of chunk g (g % 3)

    for (int g = 0; g < G; g++) {
        if (g == G - 1) cp_wait<0>(); else cp_wait<1>();
        __syncthreads();   // chunk g visible everywhere; MMA(g-1) done everywhere

        const int c = g & 3;
        if (c == 0) {
            // new MMA tile: decode, stage labels/norms, clear accumulators
            decode_tile((int)blockIdx.x + (g >> 2) * (int)gridDim.x, ntb, mbi, mbj);
            if (tid < 128) { labi[tid] = g_lab[mbi + tid]; xxi[tid] = g_xx[mbi + tid]; }
            else { labj[tid - 128] = g_lab[mbj + tid - 128]; xxj[tid - 128] = g_xx[mbj + tid - 128]; }
#pragma unroll
            for (int a = 0; a < 2; a++)
#pragma unroll
                for (int b = 0; b < 8; b++)
#pragma unroll
                    for (int e = 0; e < 4; e++) acc[a][b][e] = 0.f;
        }

        // issue load for chunk g+2 (stage (g+2)%3); crosses tile boundaries
        const int cl = g + 2;
        if (cl < G) {
            if ((cl & 3) == 0)
                decode_tile((int)blockIdx.x + (cl >> 2) * (int)gridDim.x, ntb, lbi, lbj);
            int stl = stg + 2; if (stl >= NSTG) stl -= NSTG;
            load_chunk(sb + SM_STAGE + stl * STAGE_SZ, lbi, lbj, cl & 3, tid);
        }
        CP_COMMIT();

        mma_chunk_w(acc, sb + SM_STAGE + stg * STAGE_SZ, m_base, n_base, lane);
        if (++stg == NSTG) stg = 0;

        if (c == 3) {
            // ---- epilogue: d^2 in-place, row + column masked reductions ----
            float xi[4]; int li[4];
#pragma unroll
            for (int mt = 0; mt < 2; mt++)
#pragma unroll
                for (int rh = 0; rh < 2; rh++) {
                    int r = m_base + mt * 16 + (lane >> 2) + 8 * rh;
                    xi[mt * 2 + rh] = xxi[r];
                    li[mt * 2 + rh] = labi[r];
                }
            float xj[16]; int lj[16];
#pragma unroll
            for (int nt = 0; nt < 8; nt++)
#pragma unroll
                for (int cc = 0; cc < 2; cc++) {
                    int cidx = n_base + nt * 8 + (lane & 3) * 2 + cc;
                    xj[nt * 2 + cc] = xxj[cidx];
                    lj[nt * 2 + cc] = labj[cidx];
                }
#pragma unroll
            for (int mt = 0; mt < 2; mt++)
#pragma unroll
                for (int nt = 0; nt < 8; nt++)
#pragma unroll
                    for (int e = 0; e < 4; e++) {
                        int rh = e >> 1, cc = e & 1;
                        acc[mt][nt][e] = fmaf(-2.f, acc[mt][nt][e],
                                              xi[mt * 2 + rh] + xj[nt * 2 + cc]);
                    }

            // row direction: rows of block mbi vs cols of block mbj
#pragma unroll
            for (int mt = 0; mt < 2; mt++)
#pragma unroll
                for (int rh = 0; rh < 2; rh++) {
                    float pm = -1.f, nm = FLT_MAX;
                    const int L = li[mt * 2 + rh];
#pragma unroll
                    for (int nt = 0; nt < 8; nt++)
#pragma unroll
                        for (int cc = 0; cc < 2; cc++) {
                            float v = acc[mt][nt][rh * 2 + cc];
                            if (L == lj[nt * 2 + cc]) pm = fmaxf(pm, v);
                            else                      nm = fminf(nm, v);
                        }
                    pm = fmaxf(pm, __shfl_xor_sync(0xffffffffu, pm, 1));
                    pm = fmaxf(pm, __shfl_xor_sync(0xffffffffu, pm, 2));
                    nm = fminf(nm, __shfl_xor_sync(0xffffffffu, nm, 1));
                    nm = fminf(nm, __shfl_xor_sync(0xffffffffu, nm, 2));
                    if ((lane & 3) == 0) {
                        int gi = mbi + m_base + mt * 16 + (lane >> 2) + 8 * rh;
                        atomicMax(&g_posmax[gi], __float_as_int(pm));
                        atomicMin(&g_negmin[gi], __float_as_int(nm));
                    }
                }

            // column direction (symmetry): rows of block mbj vs cols of block mbi
#pragma unroll
            for (int nt = 0; nt < 8; nt++)
#pragma unroll
                for (int cc = 0; cc < 2; cc++) {
                    float pm = -1.f, nm = FLT_MAX;
                    const int L = lj[nt * 2 + cc];
#pragma unroll
                    for (int mt = 0; mt < 2; mt++)
#pragma unroll
                        for (int rh = 0; rh < 2; rh++) {
                            float v = acc[mt][nt][rh * 2 + cc];
                            if (L == li[mt * 2 + rh]) pm = fmaxf(pm, v);
                            else                      nm = fminf(nm, v);
                        }
                    pm = fmaxf(pm, __shfl_xor_sync(0xffffffffu, pm, 4));
                    pm = fmaxf(pm, __shfl_xor_sync(0xffffffffu, pm, 8));
                    pm = fmaxf(pm, __shfl_xor_sync(0xffffffffu, pm, 16));
                    nm = fminf(nm, __shfl_xor_sync(0xffffffffu, nm, 4));
                    nm = fminf(nm, __shfl_xor_sync(0xffffffffu, nm, 8));
                    nm = fminf(nm, __shfl_xor_sync(0xffffffffu, nm, 16));
                    if (lane < 4) {
                        int gj = mbj + n_base + nt * 8 + (lane & 3) * 2 + cc;
                        atomicMax(&g_posmax[gj], __float_as_int(pm));
                        atomicMin(&g_negmin[gj], __float_as_int(nm));
                    }
                }
        }
    }
}

// ---------------------------------------------------------------------------
// Finalize: sqrt, validity, margin ranking loss mean.
// ---------------------------------------------------------------------------
__global__ void finalize_kernel(float* __restrict__ out, int n) {
    __shared__ float ss[256];
    __shared__ float sc[256];
    float sum = 0.f, cnt = 0.f;
    for (int i = threadIdx.x; i < n; i += 256) {
        float ap2 = __int_as_float(g_posmax[i]);
        float ap  = sqrtf(fmaxf(ap2, 1e-12f));
        float nm2 = __int_as_float(g_negmin[i]);
        bool  has_neg = nm2 < 1e30f;
        float an  = has_neg ? sqrtf(fmaxf(nm2, 1e-12f)) : 0.f;
        bool  valid = (ap < 1000000.0f) && (an > 0.f);
        if (valid) {
            sum += fmaxf(0.3f + ap - an, 0.f);
            cnt += 1.f;
        }
    }
    ss[threadIdx.x] = sum;
    sc[threadIdx.x] = cnt;
    __syncthreads();
    for (int o = 128; o; o >>= 1) {
        if (threadIdx.x < o) {
            ss[threadIdx.x] += ss[threadIdx.x + o];
            sc[threadIdx.x] += sc[threadIdx.x + o];
        }
        __syncthreads();
    }
    if (threadIdx.x == 0)
        out[0] = (sc[0] > 0.f) ? ss[0] / fmaxf(sc[0], 1.f) : 0.f;
}

// ---------------------------------------------------------------------------
extern "C" void kernel_launch(void* const* d_in, const int* in_sizes, int n_in,
                              void* d_out, int out_size) {
    const float* feat   = (const float*)d_in[0];
    const int*   labels = (const int*)d_in[1];   // int32/int64 auto-detected
    int n = in_sizes[1];                         // 4096

    cudaFuncSetAttribute(tile_kernel, cudaFuncAttributeMaxDynamicSharedMemorySize,
                         SMEM_TOTAL);

    prep_kernel<<<(n + 7) / 8, 256>>>(feat, labels, n);
    tile_kernel<<<148, 256, SMEM_TOTAL>>>(n);
    finalize_kernel<<<1, 256>>>((float*)d_out, n);
}

// round 5
// speedup vs baseline: 1.0422x; 1.0422x over previous
#include <cuda_runtime.h>
#include <cuda_bf16.h>
#include <float.h>
#include <stdint.h>

#define NMAX 4096
#define DIMK 256              // fp32 features per row
#define KC   64               // bf16 elements per K-chunk (128 bytes per row)
#define NCH  (DIMK / KC)      // 4 chunks per tile
#define NSTG 3                // smem pipeline stages
#define NTHR 512

// ---------------- device scratch (no allocs allowed) ----------------
__device__ int   g_posmax[NMAX];                 // max d^2 over positives, float bits
__device__ int   g_negmin[NMAX];                 // min d^2 over negatives, float bits
__device__ float g_xx[NMAX];                     // squared norms
__device__ int   g_lab[NMAX];                    // normalized labels
__device__ __align__(16) __nv_bfloat16 g_hi[NMAX * DIMK];
__device__ __align__(16) __nv_bfloat16 g_lo[NMAX * DIMK];

// ---------------- baseline-ISA PTX helpers (sm_80+) ----------------
__device__ __forceinline__ uint32_t s2u(const void* p) {
    uint32_t a;
    asm("{ .reg .u64 t; cvta.to.shared.u64 t, %1; cvt.u32.u64 %0, t; }" : "=r"(a) : "l"(p));
    return a;
}
__device__ __forceinline__ void cp16(uint32_t saddr, const void* g) {
    asm volatile("cp.async.cg.shared.global [%0], [%1], 16;" :: "r"(saddr), "l"(g) : "memory");
}
#define CP_COMMIT() asm volatile("cp.async.commit_group;" ::: "memory")
template <int N> __device__ __forceinline__ void cp_wait() {
    asm volatile("cp.async.wait_group %0;" :: "n"(N) : "memory");
}
__device__ __forceinline__ void ldsm4(uint32_t* r, uint32_t a) {
    asm volatile("ldmatrix.sync.aligned.m8n8.x4.shared.b16 {%0,%1,%2,%3}, [%4];"
                 : "=r"(r[0]), "=r"(r[1]), "=r"(r[2]), "=r"(r[3]) : "r"(a));
}
__device__ __forceinline__ void mma16816(float* d, const uint32_t* a,
                                         uint32_t b0, uint32_t b1) {
    asm volatile(
        "mma.sync.aligned.m16n8k16.row.col.f32.bf16.bf16.f32 "
        "{%0,%1,%2,%3}, {%4,%5,%6,%7}, {%8,%9}, {%0,%1,%2,%3};"
        : "+f"(d[0]), "+f"(d[1]), "+f"(d[2]), "+f"(d[3])
        : "r"(a[0]), "r"(a[1]), "r"(a[2]), "r"(a[3]), "r"(b0), "r"(b1));
}
#define SWZ(x) ((x) ^ ((((uint32_t)(x)) >> 3) & 0x70))

// SMEM layout (relative to 128-aligned base)
#define SM_LABI  0            // 128 int
#define SM_XXI   512          // 128 float
#define SM_LABJ  1024
#define SM_XXJ   1536
#define SM_STAGE 2048         // NSTG stages x 64KB; 4 components of 16KB each
#define STAGE_SZ 65536
#define COMP_SZ  16384
#define SMEM_TOTAL (SM_STAGE + NSTG * STAGE_SZ + 128)

// ---------------------------------------------------------------------------
// Prep: bf16 hi/lo split, squared norms, label normalization, init.
// ---------------------------------------------------------------------------
__global__ void prep_kernel(const float* __restrict__ feat,
                            const int* __restrict__ lab_raw, int n) {
    int row  = blockIdx.x * 8 + (threadIdx.x >> 5);
    int lane = threadIdx.x & 31;
    if (row >= n) return;

    const float4* p = (const float4*)(feat + (size_t)row * DIMK);
    float4 v0 = p[lane];
    float4 v1 = p[lane + 32];

    float s = v0.x * v0.x + v0.y * v0.y + v0.z * v0.z + v0.w * v0.w
            + v1.x * v1.x + v1.y * v1.y + v1.z * v1.z + v1.w * v1.w;

    float4 vv[2] = {v0, v1};
#pragma unroll
    for (int i = 0; i < 2; i++) {
        float4 v = vv[i];
        __nv_bfloat16 hx = __float2bfloat16(v.x), hy = __float2bfloat16(v.y);
        __nv_bfloat16 hz = __float2bfloat16(v.z), hw = __float2bfloat16(v.w);
        int base = row * DIMK + (lane + 32 * i) * 4;
        __nv_bfloat162* H = (__nv_bfloat162*)(g_hi + base);
        __nv_bfloat162 h0; h0.x = hx; h0.y = hy;
        __nv_bfloat162 h1; h1.x = hz; h1.y = hw;
        H[0] = h0; H[1] = h1;
        __nv_bfloat162* L = (__nv_bfloat162*)(g_lo + base);
        __nv_bfloat162 l0, l1;
        l0.x = __float2bfloat16(v.x - __bfloat162float(hx));
        l0.y = __float2bfloat16(v.y - __bfloat162float(hy));
        l1.x = __float2bfloat16(v.z - __bfloat162float(hz));
        l1.y = __float2bfloat16(v.w - __bfloat162float(hw));
        L[0] = l0; L[1] = l1;
    }
#pragma unroll
    for (int o = 16; o; o >>= 1) s += __shfl_xor_sync(0xffffffffu, s, o);

    if (lane == 0) {
        g_xx[row]     = s;
        g_posmax[row] = 0;                       // bits of +0.0f
        g_negmin[row] = __float_as_int(FLT_MAX);
    }
    if (lane == 1) {
        bool is64 = true;
#pragma unroll
        for (int i = 0; i < 32; i++)
            if (lab_raw[2 * i + 1] != 0) { is64 = false; break; }
        g_lab[row] = is64 ? lab_raw[2 * row] : lab_raw[row];
    }
}

// ---------------------------------------------------------------------------
__device__ __forceinline__ void decode_tile(int t, int ntb, int& bi, int& bj) {
    int ti = 0;
    while (t >= ntb - ti) { t -= ntb - ti; ti++; }
    bi = ti << 7;
    bj = (ti + t) << 7;
}

// Load one 64-wide K chunk (4 components x 128 rows x 128B, SW128 swizzled)
__device__ __forceinline__ void load_chunk(uint32_t stage, int bi, int bj,
                                           int c, int tid) {
    const int row  = tid & 127;
    const int quad = tid >> 7;       // 0..3: which 32B quarter of the row
    const size_t ga = (size_t)(bi + row) * DIMK + c * KC;
    const size_t gb = (size_t)(bj + row) * DIMK + c * KC;
    const char* Ah = (const char*)(g_hi + ga);
    const char* Al = (const char*)(g_lo + ga);
    const char* Bh = (const char*)(g_hi + gb);
    const char* Bl = (const char*)(g_lo + gb);
    const uint32_t ro = (uint32_t)row * 128;
#pragma unroll
    for (int q = 0; q < 2; q++) {
        uint32_t off = quad * 32 + q * 16;
        uint32_t so  = SWZ(ro + off);
        cp16(stage + 0 * COMP_SZ + so, Ah + off);
        cp16(stage + 1 * COMP_SZ + so, Al + off);
        cp16(stage + 2 * COMP_SZ + so, Bh + off);
        cp16(stage + 3 * COMP_SZ + so, Bl + off);
    }
}

// ---------------------------------------------------------------------------
// MMA over one chunk, per-warp 32x32 output.
// 3 separate passes (hi*hi, hi*lo, lo*hi) so consecutive HMMAs never share
// an accumulator -> no RAW stalls.
// ---------------------------------------------------------------------------
__device__ __forceinline__ void mma_chunk_w(float acc[2][4][4], uint32_t st,
                                            int m_base, int n_base, int lane) {
    const uint32_t sAh = st, sAl = st + COMP_SZ;
    const uint32_t sBh = st + 2 * COMP_SZ, sBl = st + 3 * COMP_SZ;
#pragma unroll
    for (int s = 0; s < 4; s++) {                 // k16 steps within KC=64
        const uint32_t koff = (uint32_t)s * 32 + ((lane >> 4) << 4);
        uint32_t ah[2][4], al[2][4], bh[2][4], bl[2][4];
#pragma unroll
        for (int mt = 0; mt < 2; mt++) {
            uint32_t ad = SWZ((uint32_t)(m_base + mt * 16 + (lane & 15)) * 128 + koff);
            ldsm4(ah[mt], sAh + ad);
            ldsm4(al[mt], sAl + ad);
        }
#pragma unroll
        for (int p = 0; p < 2; p++) {
            uint32_t bd = SWZ((uint32_t)(n_base + p * 16 + (lane & 15)) * 128 + koff);
            ldsm4(bh[p], sBh + bd);
            ldsm4(bl[p], sBl + bd);
        }
        // pass 1: hi*hi
#pragma unroll
        for (int mt = 0; mt < 2; mt++)
#pragma unroll
            for (int nt = 0; nt < 4; nt++) {
                const int p = nt >> 1, q = nt & 1;
                mma16816(acc[mt][nt], ah[mt], bh[p][q], bh[p][2 + q]);
            }
        // pass 2: hi*lo
#pragma unroll
        for (int mt = 0; mt < 2; mt++)
#pragma unroll
            for (int nt = 0; nt < 4; nt++) {
                const int p = nt >> 1, q = nt & 1;
                mma16816(acc[mt][nt], ah[mt], bl[p][q], bl[p][2 + q]);
            }
        // pass 3: lo*hi
#pragma unroll
        for (int mt = 0; mt < 2; mt++)
#pragma unroll
            for (int nt = 0; nt < 4; nt++) {
                const int p = nt >> 1, q = nt & 1;
                mma16816(acc[mt][nt], al[mt], bh[p][q], bh[p][2 + q]);
            }
    }
}

// ---------------------------------------------------------------------------
// Persistent flat-stream kernel: 3-stage ring, cross-tile prefetch,
// 16 warps (4x4 grid, 32x32 each), dual-direction masked epilogue.
// ---------------------------------------------------------------------------
__global__ void __launch_bounds__(NTHR, 1) tile_kernel(int n) {
    extern __shared__ char smem_raw[];
    uint32_t sb_raw = s2u(smem_raw);
    uint32_t pad = (128u - (sb_raw & 127u)) & 127u;
    char* sm = smem_raw + pad;
    uint32_t sb = sb_raw + pad;

    int*   labi = (int*)(sm + SM_LABI);
    float* xxi  = (float*)(sm + SM_XXI);
    int*   labj = (int*)(sm + SM_LABJ);
    float* xxj  = (float*)(sm + SM_XXJ);

    const int tid = threadIdx.x, lane = tid & 31, w = tid >> 5;
    const int m_base = (w & 3) * 32;     // 4 warps along M
    const int n_base = (w >> 2) * 32;    // 4 warps along N

    const int ntb = n >> 7;
    const int T   = ntb * (ntb + 1) / 2;          // upper triangle incl. diagonal
    const int myT = (T - (int)blockIdx.x + (int)gridDim.x - 1) / (int)gridDim.x;
    const int G   = myT * NCH;                    // chunks this CTA streams
    if (G == 0) return;

    int lbi, lbj;                                 // tile of chunk being loaded
    int mbi = 0, mbj = 0;                         // tile of chunk being MMA'd
    decode_tile(blockIdx.x, ntb, lbi, lbj);

    load_chunk(sb + SM_STAGE + 0 * STAGE_SZ, lbi, lbj, 0, tid);
    CP_COMMIT();
    load_chunk(sb + SM_STAGE + 1 * STAGE_SZ, lbi, lbj, 1, tid);
    CP_COMMIT();

    float acc[2][4][4];
    int stg = 0;

    for (int g = 0; g < G; g++) {
        if (g == G - 1) cp_wait<0>(); else cp_wait<1>();
        __syncthreads();   // chunk g visible; MMA(g-1) done everywhere

        const int c = g & 3;
        if (c == 0) {
            decode_tile((int)blockIdx.x + (g >> 2) * (int)gridDim.x, ntb, mbi, mbj);
            if (tid < 128) { labi[tid] = g_lab[mbi + tid]; xxi[tid] = g_xx[mbi + tid]; }
            else if (tid < 256) {
                labj[tid - 128] = g_lab[mbj + tid - 128];
                xxj[tid - 128]  = g_xx[mbj + tid - 128];
            }
#pragma unroll
            for (int a = 0; a < 2; a++)
#pragma unroll
                for (int b = 0; b < 4; b++)
#pragma unroll
                    for (int e = 0; e < 4; e++) acc[a][b][e] = 0.f;
        }

        const int cl = g + 2;                     // prefetch chunk g+2
        if (cl < G) {
            if ((cl & 3) == 0)
                decode_tile((int)blockIdx.x + (cl >> 2) * (int)gridDim.x, ntb, lbi, lbj);
            int stl = stg + 2; if (stl >= NSTG) stl -= NSTG;
            load_chunk(sb + SM_STAGE + stl * STAGE_SZ, lbi, lbj, cl & 3, tid);
        }
        CP_COMMIT();

        mma_chunk_w(acc, sb + SM_STAGE + stg * STAGE_SZ, m_base, n_base, lane);
        if (++stg == NSTG) stg = 0;

        if (c == 3) {
            // ---- epilogue: d^2 in-place, row + column masked reductions ----
            float xi[4]; int li[4];
#pragma unroll
            for (int mt = 0; mt < 2; mt++)
#pragma unroll
                for (int rh = 0; rh < 2; rh++) {
                    int r = m_base + mt * 16 + (lane >> 2) + 8 * rh;
                    xi[mt * 2 + rh] = xxi[r];
                    li[mt * 2 + rh] = labi[r];
                }
            float xj[8]; int lj[8];
#pragma unroll
            for (int nt = 0; nt < 4; nt++)
#pragma unroll
                for (int cc = 0; cc < 2; cc++) {
                    int cidx = n_base + nt * 8 + (lane & 3) * 2 + cc;
                    xj[nt * 2 + cc] = xxj[cidx];
                    lj[nt * 2 + cc] = labj[cidx];
                }
#pragma unroll
            for (int mt = 0; mt < 2; mt++)
#pragma unroll
                for (int nt = 0; nt < 4; nt++)
#pragma unroll
                    for (int e = 0; e < 4; e++) {
                        int rh = e >> 1, cc = e & 1;
                        acc[mt][nt][e] = fmaf(-2.f, acc[mt][nt][e],
                                              xi[mt * 2 + rh] + xj[nt * 2 + cc]);
                    }

            // row direction: rows of block mbi vs cols of block mbj
#pragma unroll
            for (int mt = 0; mt < 2; mt++)
#pragma unroll
                for (int rh = 0; rh < 2; rh++) {
                    float pm = -1.f, nm = FLT_MAX;
                    const int L = li[mt * 2 + rh];
#pragma unroll
                    for (int nt = 0; nt < 4; nt++)
#pragma unroll
                        for (int cc = 0; cc < 2; cc++) {
                            float v = acc[mt][nt][rh * 2 + cc];
                            if (L == lj[nt * 2 + cc]) pm = fmaxf(pm, v);
                            else                      nm = fminf(nm, v);
                        }
                    pm = fmaxf(pm, __shfl_xor_sync(0xffffffffu, pm, 1));
                    pm = fmaxf(pm, __shfl_xor_sync(0xffffffffu, pm, 2));
                    nm = fminf(nm, __shfl_xor_sync(0xffffffffu, nm, 1));
                    nm = fminf(nm, __shfl_xor_sync(0xffffffffu, nm, 2));
                    if ((lane & 3) == 0) {
                        int gi = mbi + m_base + mt * 16 + (lane >> 2) + 8 * rh;
                        atomicMax(&g_posmax[gi], __float_as_int(pm));
                        atomicMin(&g_negmin[gi], __float_as_int(nm));
                    }
                }

            // column direction (symmetry): rows of block mbj vs cols of block mbi
#pragma unroll
            for (int nt = 0; nt < 4; nt++)
#pragma unroll
                for (int cc = 0; cc < 2; cc++) {
                    float pm = -1.f, nm = FLT_MAX;
                    const int L = lj[nt * 2 + cc];
#pragma unroll
                    for (int mt = 0; mt < 2; mt++)
#pragma unroll
                        for (int rh = 0; rh < 2; rh++) {
                            float v = acc[mt][nt][rh * 2 + cc];
                            if (L == li[mt * 2 + rh]) pm = fmaxf(pm, v);
                            else                      nm = fminf(nm, v);
                        }
                    pm = fmaxf(pm, __shfl_xor_sync(0xffffffffu, pm, 4));
                    pm = fmaxf(pm, __shfl_xor_sync(0xffffffffu, pm, 8));
                    pm = fmaxf(pm, __shfl_xor_sync(0xffffffffu, pm, 16));
                    nm = fminf(nm, __shfl_xor_sync(0xffffffffu, nm, 4));
                    nm = fminf(nm, __shfl_xor_sync(0xffffffffu, nm, 8));
                    nm = fminf(nm, __shfl_xor_sync(0xffffffffu, nm, 16));
                    if (lane < 4) {
                        int gj = mbj + n_base + nt * 8 + (lane & 3) * 2 + cc;
                        atomicMax(&g_posmax[gj], __float_as_int(pm));
                        atomicMin(&g_negmin[gj], __float_as_int(nm));
                    }
                }
        }
    }
}

// ---------------------------------------------------------------------------
// Finalize: sqrt, validity, margin ranking loss mean.
// ---------------------------------------------------------------------------
__global__ void finalize_kernel(float* __restrict__ out, int n) {
    __shared__ float ss[256];
    __shared__ float sc[256];
    float sum = 0.f, cnt = 0.f;
    for (int i = threadIdx.x; i < n; i += 256) {
        float ap2 = __int_as_float(g_posmax[i]);
        float ap  = sqrtf(fmaxf(ap2, 1e-12f));
        float nm2 = __int_as_float(g_negmin[i]);
        bool  has_neg = nm2 < 1e30f;
        float an  = has_neg ? sqrtf(fmaxf(nm2, 1e-12f)) : 0.f;
        bool  valid = (ap < 1000000.0f) && (an > 0.f);
        if (valid) {
            sum += fmaxf(0.3f + ap - an, 0.f);
            cnt += 1.f;
        }
    }
    ss[threadIdx.x] = sum;
    sc[threadIdx.x] = cnt;
    __syncthreads();
    for (int o = 128; o; o >>= 1) {
        if (threadIdx.x < o) {
            ss[threadIdx.x] += ss[threadIdx.x + o];
            sc[threadIdx.x] += sc[threadIdx.x + o];
        }
        __syncthreads();
    }
    if (threadIdx.x == 0)
        out[0] = (sc[0] > 0.f) ? ss[0] / fmaxf(sc[0], 1.f) : 0.f;
}

// ---------------------------------------------------------------------------
extern "C" void kernel_launch(void* const* d_in, const int* in_sizes, int n_in,
                              void* d_out, int out_size) {
    const float* feat   = (const float*)d_in[0];
    const int*   labels = (const int*)d_in[1];   // int32/int64 auto-detected
    int n = in_sizes[1];                         // 4096

    cudaFuncSetAttribute(tile_kernel, cudaFuncAttributeMaxDynamicSharedMemorySize,
                         SMEM_TOTAL);

    prep_kernel<<<(n + 7) / 8, 256>>>(feat, labels, n);
    tile_kernel<<<148, NTHR, SMEM_TOTAL>>>(n);
    finalize_kernel<<<1, 256>>>((float*)d_out, n);
}

// round 7
// speedup vs baseline: 1.7485x; 1.6776x over previous
#include <cuda_runtime.h>
#include <cuda_fp16.h>
#include <float.h>
#include <stdint.h>

#define NMAX 4096
#define DIMK 256              // fp32 features per row
#define KC   64               // fp16 elements per K-chunk (128 bytes per row)
#define NCH  (DIMK / KC)      // 4 chunks per tile
#define NSTG 4                // smem pipeline stages
#define PFD  3                // prefetch distance (chunks)
#define NTHR 512

// ---------------- device scratch (no allocs allowed) ----------------
__device__ int   g_posmax[NMAX];                 // max d^2 over positives, float bits
__device__ int   g_negmin[NMAX];                 // min d^2 over negatives, float bits
__device__ float g_xx[NMAX];                     // squared norms (exact fp32)
__device__ int   g_lab[NMAX];                    // normalized labels
__device__ __align__(16) __half g_f16[NMAX * DIMK];

// ---------------- baseline-ISA PTX helpers (sm_80+) ----------------
__device__ __forceinline__ uint32_t s2u(const void* p) {
    uint32_t a;
    asm("{ .reg .u64 t; cvta.to.shared.u64 t, %1; cvt.u32.u64 %0, t; }" : "=r"(a) : "l"(p));
    return a;
}
__device__ __forceinline__ void cp16(uint32_t saddr, const void* g) {
    asm volatile("cp.async.cg.shared.global [%0], [%1], 16;" :: "r"(saddr), "l"(g) : "memory");
}
#define CP_COMMIT() asm volatile("cp.async.commit_group;" ::: "memory")
template <int N> __device__ __forceinline__ void cp_wait() {
    asm volatile("cp.async.wait_group %0;" :: "n"(N) : "memory");
}
__device__ __forceinline__ void ldsm4(uint32_t* r, uint32_t a) {
    asm volatile("ldmatrix.sync.aligned.m8n8.x4.shared.b16 {%0,%1,%2,%3}, [%4];"
                 : "=r"(r[0]), "=r"(r[1]), "=r"(r[2]), "=r"(r[3]) : "r"(a));
}
__device__ __forceinline__ void mma16816(float* d, const uint32_t* a,
                                         uint32_t b0, uint32_t b1) {
    asm volatile(
        "mma.sync.aligned.m16n8k16.row.col.f32.f16.f16.f32 "
        "{%0,%1,%2,%3}, {%4,%5,%6,%7}, {%8,%9}, {%0,%1,%2,%3};"
        : "+f"(d[0]), "+f"(d[1]), "+f"(d[2]), "+f"(d[3])
        : "r"(a[0]), "r"(a[1]), "r"(a[2]), "r"(a[3]), "r"(b0), "r"(b1));
}
#define SWZ(x) ((x) ^ ((((uint32_t)(x)) >> 3) & 0x70))

// SMEM layout (relative to 128-aligned base)
#define SM_LABI  0            // 128 int
#define SM_XXI   512          // 128 float
#define SM_LABJ  1024
#define SM_XXJ   1536
#define SM_STAGE 2048         // NSTG stages x 32KB; A comp + B comp of 16KB
#define COMP_SZ  16384
#define STAGE_SZ 32768
#define SMEM_TOTAL (SM_STAGE + NSTG * STAGE_SZ + 128)

// ---------------------------------------------------------------------------
// Prep: fp16 conversion, squared norms (exact fp32), label normalization, init.
// ---------------------------------------------------------------------------
__global__ void prep_kernel(const float* __restrict__ feat,
                            const int* __restrict__ lab_raw, int n) {
    int row  = blockIdx.x * 8 + (threadIdx.x >> 5);
    int lane = threadIdx.x & 31;
    if (row >= n) return;

    const float4* p = (const float4*)(feat + (size_t)row * DIMK);
    float4 v0 = p[lane];
    float4 v1 = p[lane + 32];

    float s = v0.x * v0.x + v0.y * v0.y + v0.z * v0.z + v0.w * v0.w
            + v1.x * v1.x + v1.y * v1.y + v1.z * v1.z + v1.w * v1.w;

    float4 vv[2] = {v0, v1};
#pragma unroll
    for (int i = 0; i < 2; i++) {
        float4 v = vv[i];
        int base = row * DIMK + (lane + 32 * i) * 4;
        __half2* H = (__half2*)(g_f16 + base);
        H[0] = __floats2half2_rn(v.x, v.y);
        H[1] = __floats2half2_rn(v.z, v.w);
    }
#pragma unroll
    for (int o = 16; o; o >>= 1) s += __shfl_xor_sync(0xffffffffu, s, o);

    if (lane == 0) {
        g_xx[row]     = s;
        g_posmax[row] = 0;                       // bits of +0.0f
        g_negmin[row] = __float_as_int(FLT_MAX);
    }
    if (lane == 1) {
        bool is64 = true;
#pragma unroll
        for (int i = 0; i < 32; i++)
            if (lab_raw[2 * i + 1] != 0) { is64 = false; break; }
        g_lab[row] = is64 ? lab_raw[2 * row] : lab_raw[row];
    }
}

// ---------------------------------------------------------------------------
__device__ __forceinline__ void decode_tile(int t, int ntb, int& bi, int& bj) {
    int ti = 0;
    while (t >= ntb - ti) { t -= ntb - ti; ti++; }
    bi = ti << 7;
    bj = (ti + t) << 7;
}

// Load one 64-wide K chunk (A + B, 128 rows x 128B each, SW128 swizzled)
__device__ __forceinline__ void load_chunk(uint32_t stage, int bi, int bj,
                                           int c, int tid) {
    const int row  = tid & 127;
    const int quad = tid >> 7;       // 0..3: which 32B quarter of the row
    const char* A = (const char*)(g_f16 + (size_t)(bi + row) * DIMK + c * KC);
    const char* B = (const char*)(g_f16 + (size_t)(bj + row) * DIMK + c * KC);
    const uint32_t ro = (uint32_t)row * 128;
#pragma unroll
    for (int q = 0; q < 2; q++) {
        uint32_t off = quad * 32 + q * 16;
        uint32_t so  = SWZ(ro + off);
        cp16(stage + so, A + off);
        cp16(stage + COMP_SZ + so, B + off);
    }
}

// ---------------------------------------------------------------------------
// MMA over one chunk, per-warp 32x32 output, single fp16 product.
// 8 distinct accumulators between dependent issues -> no RAW stalls.
// ---------------------------------------------------------------------------
__device__ __forceinline__ void mma_chunk_w(float acc[2][4][4], uint32_t st,
                                            int m_base, int n_base, int lane) {
    const uint32_t sA = st, sB = st + COMP_SZ;
#pragma unroll
    for (int s = 0; s < 4; s++) {                 // k16 steps within KC=64
        const uint32_t koff = (uint32_t)s * 32 + ((lane >> 4) << 4);
        uint32_t a[2][4], b[2][4];
#pragma unroll
        for (int mt = 0; mt < 2; mt++) {
            uint32_t ad = SWZ((uint32_t)(m_base + mt * 16 + (lane & 15)) * 128 + koff);
            ldsm4(a[mt], sA + ad);
        }
#pragma unroll
        for (int p = 0; p < 2; p++) {
            uint32_t bd = SWZ((uint32_t)(n_base + p * 16 + (lane & 15)) * 128 + koff);
            ldsm4(b[p], sB + bd);
        }
#pragma unroll
        for (int mt = 0; mt < 2; mt++)
#pragma unroll
            for (int nt = 0; nt < 4; nt++) {
                const int p = nt >> 1, q = nt & 1;
                mma16816(acc[mt][nt], a[mt], b[p][q], b[p][2 + q]);
            }
    }
}

// ---------------------------------------------------------------------------
// Persistent flat-stream kernel: 4-stage ring, distance-3 cross-tile prefetch,
// 16 warps (4x4 grid, 32x32 each), dual-direction masked epilogue.
// ---------------------------------------------------------------------------
__global__ void __launch_bounds__(NTHR, 1) tile_kernel(int n) {
    extern __shared__ char smem_raw[];
    uint32_t sb_raw = s2u(smem_raw);
    uint32_t pad = (128u - (sb_raw & 127u)) & 127u;
    char* sm = smem_raw + pad;
    uint32_t sb = sb_raw + pad;

    int*   labi = (int*)(sm + SM_LABI);
    float* xxi  = (float*)(sm + SM_XXI);
    int*   labj = (int*)(sm + SM_LABJ);
    float* xxj  = (float*)(sm + SM_XXJ);

    const int tid = threadIdx.x, lane = tid & 31, w = tid >> 5;
    const int m_base = (w & 3) * 32;     // 4 warps along M
    const int n_base = (w >> 2) * 32;    // 4 warps along N

    const int ntb = n >> 7;
    const int T   = ntb * (ntb + 1) / 2;          // upper triangle incl. diagonal
    const int myT = (T - (int)blockIdx.x + (int)gridDim.x - 1) / (int)gridDim.x;
    const int G   = myT * NCH;                    // chunks this CTA streams
    if (G == 0) return;

    int lbi, lbj;                                 // tile of chunk being loaded
    int mbi = 0, mbj = 0;                         // tile of chunk being MMA'd
    decode_tile(blockIdx.x, ntb, lbi, lbj);

    // prologue: chunks 0..PFD-1 (tile boundaries handled by decode below)
#pragma unroll
    for (int c = 0; c < PFD; c++) {
        if (c < G) {
            if ((c & 3) == 0 && c > 0)
                decode_tile((int)blockIdx.x + (c >> 2) * (int)gridDim.x, ntb, lbi, lbj);
            load_chunk(sb + SM_STAGE + c * STAGE_SZ, lbi, lbj, c & 3, tid);
        }
        CP_COMMIT();
    }

    float acc[2][4][4];
    int stg = 0;

    for (int g = 0; g < G; g++) {
        cp_wait<PFD - 1>();    // chunk g landed (empty groups keep count exact)
        __syncthreads();       // chunk g visible; MMA(g-1) done everywhere

        const int c = g & 3;
        if (c == 0) {
            decode_tile((int)blockIdx.x + (g >> 2) * (int)gridDim.x, ntb, mbi, mbj);
            if (tid < 128) { labi[tid] = g_lab[mbi + tid]; xxi[tid] = g_xx[mbi + tid]; }
            else if (tid < 256) {
                labj[tid - 128] = g_lab[mbj + tid - 128];
                xxj[tid - 128]  = g_xx[mbj + tid - 128];
            }
#pragma unroll
            for (int a = 0; a < 2; a++)
#pragma unroll
                for (int b = 0; b < 4; b++)
#pragma unroll
                    for (int e = 0; e < 4; e++) acc[a][b][e] = 0.f;
        }

        const int cl = g + PFD;                   // prefetch chunk g+PFD
        if (cl < G) {
            if ((cl & 3) == 0)
                decode_tile((int)blockIdx.x + (cl >> 2) * (int)gridDim.x, ntb, lbi, lbj);
            int stl = stg + PFD; if (stl >= NSTG) stl -= NSTG;
            load_chunk(sb + SM_STAGE + stl * STAGE_SZ, lbi, lbj, cl & 3, tid);
        }
        CP_COMMIT();

        mma_chunk_w(acc, sb + SM_STAGE + stg * STAGE_SZ, m_base, n_base, lane);
        if (++stg == NSTG) stg = 0;

        if (c == 3) {
            // ---- epilogue: d^2 in-place, row + column masked reductions ----
            float xi[4]; int li[4];
#pragma unroll
            for (int mt = 0; mt < 2; mt++)
#pragma unroll
                for (int rh = 0; rh < 2; rh++) {
                    int r = m_base + mt * 16 + (lane >> 2) + 8 * rh;
                    xi[mt * 2 + rh] = xxi[r];
                    li[mt * 2 + rh] = labi[r];
                }
            float xj[8]; int lj[8];
#pragma unroll
            for (int nt = 0; nt < 4; nt++)
#pragma unroll
                for (int cc = 0; cc < 2; cc++) {
                    int cidx = n_base + nt * 8 + (lane & 3) * 2 + cc;
                    xj[nt * 2 + cc] = xxj[cidx];
                    lj[nt * 2 + cc] = labj[cidx];
                }
#pragma unroll
            for (int mt = 0; mt < 2; mt++)
#pragma unroll
                for (int nt = 0; nt < 4; nt++)
#pragma unroll
                    for (int e = 0; e < 4; e++) {
                        int rh = e >> 1, cc = e & 1;
                        acc[mt][nt][e] = fmaf(-2.f, acc[mt][nt][e],
                                              xi[mt * 2 + rh] + xj[nt * 2 + cc]);
                    }

            // row direction: rows of block mbi vs cols of block mbj
#pragma unroll
            for (int mt = 0; mt < 2; mt++)
#pragma unroll
                for (int rh = 0; rh < 2; rh++) {
                    float pm = -1.f, nm = FLT_MAX;
                    const int L = li[mt * 2 + rh];
#pragma unroll
                    for (int nt = 0; nt < 4; nt++)
#pragma unroll
                        for (int cc = 0; cc < 2; cc++) {
                            float v = acc[mt][nt][rh * 2 + cc];
                            if (L == lj[nt * 2 + cc]) pm = fmaxf(pm, v);
                            else                      nm = fminf(nm, v);
                        }
                    pm = fmaxf(pm, __shfl_xor_sync(0xffffffffu, pm, 1));
                    pm = fmaxf(pm, __shfl_xor_sync(0xffffffffu, pm, 2));
                    nm = fminf(nm, __shfl_xor_sync(0xffffffffu, nm, 1));
                    nm = fminf(nm, __shfl_xor_sync(0xffffffffu, nm, 2));
                    if ((lane & 3) == 0) {
                        int gi = mbi + m_base + mt * 16 + (lane >> 2) + 8 * rh;
                        atomicMax(&g_posmax[gi], __float_as_int(pm));
                        atomicMin(&g_negmin[gi], __float_as_int(nm));
                    }
                }

            // column direction (symmetry): rows of block mbj vs cols of block mbi
#pragma unroll
            for (int nt = 0; nt < 4; nt++)
#pragma unroll
                for (int cc = 0; cc < 2; cc++) {
                    float pm = -1.f, nm = FLT_MAX;
                    const int L = lj[nt * 2 + cc];
#pragma unroll
                    for (int mt = 0; mt < 2; mt++)
#pragma unroll
                        for (int rh = 0; rh < 2; rh++) {
                            float v = acc[mt][nt][rh * 2 + cc];
                            if (L == li[mt * 2 + rh]) pm = fmaxf(pm, v);
                            else                      nm = fminf(nm, v);
                        }
                    pm = fmaxf(pm, __shfl_xor_sync(0xffffffffu, pm, 4));
                    pm = fmaxf(pm, __shfl_xor_sync(0xffffffffu, pm, 8));
                    pm = fmaxf(pm, __shfl_xor_sync(0xffffffffu, pm, 16));
                    nm = fminf(nm, __shfl_xor_sync(0xffffffffu, nm, 4));
                    nm = fminf(nm, __shfl_xor_sync(0xffffffffu, nm, 8));
                    nm = fminf(nm, __shfl_xor_sync(0xffffffffu, nm, 16));
                    if (lane < 4) {
                        int gj = mbj + n_base + nt * 8 + (lane & 3) * 2 + cc;
                        atomicMax(&g_posmax[gj], __float_as_int(pm));
                        atomicMin(&g_negmin[gj], __float_as_int(nm));
                    }
                }
        }
    }
}

// ---------------------------------------------------------------------------
// Finalize: sqrt, validity, margin ranking loss mean.
// ---------------------------------------------------------------------------
__global__ void finalize_kernel(float* __restrict__ out, int n) {
    __shared__ float ss[256];
    __shared__ float sc[256];
    float sum = 0.f, cnt = 0.f;
    for (int i = threadIdx.x; i < n; i += 256) {
        float ap2 = __int_as_float(g_posmax[i]);
        float ap  = sqrtf(fmaxf(ap2, 1e-12f));
        float nm2 = __int_as_float(g_negmin[i]);
        bool  has_neg = nm2 < 1e30f;
        float an  = has_neg ? sqrtf(fmaxf(nm2, 1e-12f)) : 0.f;
        bool  valid = (ap < 1000000.0f) && (an > 0.f);
        if (valid) {
            sum += fmaxf(0.3f + ap - an, 0.f);
            cnt += 1.f;
        }
    }
    ss[threadIdx.x] = sum;
    sc[threadIdx.x] = cnt;
    __syncthreads();
    for (int o = 128; o; o >>= 1) {
        if (threadIdx.x < o) {
            ss[threadIdx.x] += ss[threadIdx.x + o];
            sc[threadIdx.x] += sc[threadIdx.x + o];
        }
        __syncthreads();
    }
    if (threadIdx.x == 0)
        out[0] = (sc[0] > 0.f) ? ss[0] / fmaxf(sc[0], 1.f) : 0.f;
}

// ---------------------------------------------------------------------------
extern "C" void kernel_launch(void* const* d_in, const int* in_sizes, int n_in,
                              void* d_out, int out_size) {
    const float* feat   = (const float*)d_in[0];
    const int*   labels = (const int*)d_in[1];   // int32/int64 auto-detected
    int n = in_sizes[1];                         // 4096

    cudaFuncSetAttribute(tile_kernel, cudaFuncAttributeMaxDynamicSharedMemorySize,
                         SMEM_TOTAL);

    prep_kernel<<<(n + 7) / 8, 256>>>(feat, labels, n);
    tile_kernel<<<148, NTHR, SMEM_TOTAL>>>(n);
    finalize_kernel<<<1, 256>>>((float*)d_out, n);
}

// round 8
// speedup vs baseline: 2.2155x; 1.2671x over previous
#include <cuda_runtime.h>
#include <cuda_fp16.h>
#include <float.h>
#include <stdint.h>

#define NMAX 4096
#define DIMK 256              // fp32 features per row
#define KC   64               // fp16 elements per K-chunk (128 bytes per row)
#define NCH  (DIMK / KC)      // 4 chunks per tile
#define NSTG 4                // smem stages (== NCH; chunk-in-tile == stage)
#define NTHR 512
#define CHUNK_BYTES 16384     // one 128x64 fp16 chunk, pre-swizzled

// ---------------- device scratch (no allocs allowed) ----------------
__device__ int   g_posmax[NMAX];                 // max d^2 over positives, float bits
__device__ int   g_negmin[NMAX];                 // min d^2 over negatives, float bits
__device__ float g_xx[NMAX];                     // squared norms (exact fp32)
__device__ int   g_lab[NMAX];                    // normalized labels
// chunk-major pre-swizzled fp16 features:
// block b = row/128, chunk c = col/64 -> contiguous 16KB at ((b*4+c)<<14)
__device__ __align__(16) __half g_f16s[NMAX * DIMK];

// ---------------- PTX helpers (sm_90-baseline ISA) ----------------
__device__ __forceinline__ uint32_t s2u(const void* p) {
    uint32_t a;
    asm("{ .reg .u64 t; cvta.to.shared.u64 t, %1; cvt.u32.u64 %0, t; }" : "=r"(a) : "l"(p));
    return a;
}
#define MBAR_INIT(a, c) asm volatile("mbarrier.init.shared.b64 [%0], %1;" :: "r"(a), "r"(c) : "memory")
#define MBAR_EXPECT_TX(a, b) asm volatile("mbarrier.arrive.expect_tx.shared.b64 _, [%0], %1;" :: "r"(a), "r"(b) : "memory")
#define MBAR_ARRIVE(a) asm volatile("mbarrier.arrive.release.cta.shared.b64 _, [%0];" :: "r"(a) : "memory")
#define FENCE_ASYNC()  asm volatile("fence.proxy.async.shared::cta;" ::: "memory")
__device__ __forceinline__ void mbar_wait(uint32_t mbar, uint32_t parity) {
    asm volatile(
        "{\n\t.reg .pred P;\n\t"
        "WL_%=:\n\t"
        "mbarrier.try_wait.parity.acquire.cta.shared::cta.b64 P, [%0], %1, 0x989680;\n\t"
        "@!P bra WL_%=;\n\t}"
        :: "r"(mbar), "r"(parity) : "memory");
}
__device__ __forceinline__ void bulk_g2s(uint32_t dst, const void* src, uint32_t mbar) {
    asm volatile(
        "cp.async.bulk.shared::cluster.global.mbarrier::complete_tx::bytes "
        "[%0], [%1], %2, [%3];"
        :: "r"(dst), "l"(src), "r"((uint32_t)CHUNK_BYTES), "r"(mbar) : "memory");
}
__device__ __forceinline__ void ldsm4(uint32_t* r, uint32_t a) {
    asm volatile("ldmatrix.sync.aligned.m8n8.x4.shared.b16 {%0,%1,%2,%3}, [%4];"
                 : "=r"(r[0]), "=r"(r[1]), "=r"(r[2]), "=r"(r[3]) : "r"(a));
}
__device__ __forceinline__ void mma16816(float* d, const uint32_t* a,
                                         uint32_t b0, uint32_t b1) {
    asm volatile(
        "mma.sync.aligned.m16n8k16.row.col.f32.f16.f16.f32 "
        "{%0,%1,%2,%3}, {%4,%5,%6,%7}, {%8,%9}, {%0,%1,%2,%3};"
        : "+f"(d[0]), "+f"(d[1]), "+f"(d[2]), "+f"(d[3])
        : "r"(a[0]), "r"(a[1]), "r"(a[2]), "r"(a[3]), "r"(b0), "r"(b1));
}
#define SWZ(x) ((x) ^ ((((uint32_t)(x)) >> 3) & 0x70))

// SMEM layout (relative to 1024-aligned base)
#define SM_FULL   0           // 4 x 8B mbarriers
#define SM_EMPTY  64          // 4 x 8B mbarriers
#define SM_STAGE  1024        // 4 stages x 32KB (A 16KB + B 16KB)
#define STAGE_SZ  32768
#define SMEM_TOTAL (SM_STAGE + NSTG * STAGE_SZ + 1024)

// ---------------------------------------------------------------------------
// Prep: fp16 convert into chunk-major PRE-SWIZZLED layout, exact fp32 norms,
// label normalization, reduction init. One warp per row; lane owns 8 cols.
// ---------------------------------------------------------------------------
__global__ void prep_kernel(const float* __restrict__ feat,
                            const int* __restrict__ lab_raw, int n) {
    int row  = blockIdx.x * 8 + (threadIdx.x >> 5);
    int lane = threadIdx.x & 31;
    if (row >= n) return;

    const float4* p = (const float4*)(feat + (size_t)row * DIMK);
    float4 v0 = p[2 * lane];          // cols lane*8 .. lane*8+3
    float4 v1 = p[2 * lane + 1];      // cols lane*8+4 .. lane*8+7

    float s = v0.x * v0.x + v0.y * v0.y + v0.z * v0.z + v0.w * v0.w
            + v1.x * v1.x + v1.y * v1.y + v1.z * v1.z + v1.w * v1.w;

    // pack 8 fp16 (one 16B granule) and store to swizzled chunk-major address
    __half2 h0 = __floats2half2_rn(v0.x, v0.y);
    __half2 h1 = __floats2half2_rn(v0.z, v0.w);
    __half2 h2 = __floats2half2_rn(v1.x, v1.y);
    __half2 h3 = __floats2half2_rn(v1.z, v1.w);
    uint4 pk;
    pk.x = *(uint32_t*)&h0; pk.y = *(uint32_t*)&h1;
    pk.z = *(uint32_t*)&h2; pk.w = *(uint32_t*)&h3;

    const int blk = row >> 7;                 // 128-row block
    const int c   = lane >> 3;                // chunk = (lane*8)/64
    const uint32_t in_off = SWZ(((uint32_t)(row & 127)) * 128 + (lane & 7) * 16);
    char* dst = (char*)g_f16s + (((size_t)blk * NCH + c) << 14) + in_off;
    *(uint4*)dst = pk;

#pragma unroll
    for (int o = 16; o; o >>= 1) s += __shfl_xor_sync(0xffffffffu, s, o);

    if (lane == 0) {
        g_xx[row]     = s;
        g_posmax[row] = 0;                       // bits of +0.0f
        g_negmin[row] = __float_as_int(FLT_MAX);
    }
    if (lane == 1) {
        bool is64 = true;
#pragma unroll
        for (int i = 0; i < 32; i++)
            if (lab_raw[2 * i + 1] != 0) { is64 = false; break; }
        g_lab[row] = is64 ? lab_raw[2 * row] : lab_raw[row];
    }
}

// ---------------------------------------------------------------------------
__device__ __forceinline__ void decode_tile(int t, int ntb, int& bi, int& bj) {
    int ti = 0;
    while (t >= ntb - ti) { t -= ntb - ti; ti++; }
    bi = ti << 7;
    bj = (ti + t) << 7;
}

// MMA over one chunk, per-warp 32x32 output (fp16 single product).
__device__ __forceinline__ void mma_chunk_w(float acc[2][4][4], uint32_t st,
                                            int m_base, int n_base, int lane) {
    const uint32_t sA = st, sB = st + CHUNK_BYTES;
#pragma unroll
    for (int s = 0; s < 4; s++) {                 // k16 steps within KC=64
        const uint32_t koff = (uint32_t)s * 32 + ((lane >> 4) << 4);
        uint32_t a[2][4], b[2][4];
#pragma unroll
        for (int mt = 0; mt < 2; mt++) {
            uint32_t ad = SWZ((uint32_t)(m_base + mt * 16 + (lane & 15)) * 128 + koff);
            ldsm4(a[mt], sA + ad);
        }
#pragma unroll
        for (int p = 0; p < 2; p++) {
            uint32_t bd = SWZ((uint32_t)(n_base + p * 16 + (lane & 15)) * 128 + koff);
            ldsm4(b[p], sB + bd);
        }
#pragma unroll
        for (int mt = 0; mt < 2; mt++)
#pragma unroll
            for (int nt = 0; nt < 4; nt++) {
                const int p = nt >> 1, q = nt & 1;
                mma16816(acc[mt][nt], a[mt], b[p][q], b[p][2 + q]);
            }
    }
}

// ---------------------------------------------------------------------------
// Persistent kernel: bulk-copy producer (1 thread) + mbarrier ring (4 stages),
// 16 warps (4x4, 32x32 each), dual-direction masked epilogue from gmem xx/lab.
// ---------------------------------------------------------------------------
__global__ void __launch_bounds__(NTHR, 1) tile_kernel(int n) {
    extern __shared__ char smem_raw[];
    uint32_t sb_raw = s2u(smem_raw);
    uint32_t pad = (1024u - (sb_raw & 1023u)) & 1023u;
    uint32_t sb = sb_raw + pad;

    const int tid = threadIdx.x, lane = tid & 31, w = tid >> 5;
    const int m_base = (w & 3) * 32;     // 4 warps along M
    const int n_base = (w >> 2) * 32;    // 4 warps along N

    const int ntb = n >> 7;
    const int T   = ntb * (ntb + 1) / 2;          // upper triangle incl. diagonal
    const int myT = (T - (int)blockIdx.x + (int)gridDim.x - 1) / (int)gridDim.x;
    const int G   = myT * NCH;                    // chunks this CTA streams
    if (G == 0) return;

    if (tid == 0) {
#pragma unroll
        for (int s = 0; s < NSTG; s++) {
            MBAR_INIT(sb + SM_FULL + s * 8, 1);
            MBAR_INIT(sb + SM_EMPTY + s * 8, 16);
        }
    }
    __syncthreads();

    // prologue: issue chunks 0..3 (all of this CTA's first tile)
    if (tid == 0) {
        int bi0, bj0;
        decode_tile(blockIdx.x, ntb, bi0, bj0);
        const char* Abase = (const char*)g_f16s + (((size_t)(bi0 >> 7) * NCH) << 14);
        const char* Bbase = (const char*)g_f16s + (((size_t)(bj0 >> 7) * NCH) << 14);
#pragma unroll
        for (int c = 0; c < NSTG; c++) {
            if (c < G) {
                uint32_t fb = sb + SM_FULL + c * 8;
                MBAR_EXPECT_TX(fb, 2 * CHUNK_BYTES);
                uint32_t st = sb + SM_STAGE + c * STAGE_SZ;
                bulk_g2s(st, Abase + ((size_t)c << 14), fb);
                bulk_g2s(st + CHUNK_BYTES, Bbase + ((size_t)c << 14), fb);
            }
        }
    }

    float acc[2][4][4];
    int mbi = 0, mbj = 0;

    for (int g = 0; g < G; g++) {
        const int s = g & 3;                      // stage == chunk-in-tile
        const int k = g >> 2;                     // use index / tile ordinal

        mbar_wait(sb + SM_FULL + s * 8, (uint32_t)(k & 1));

        if (s == 0) {
            decode_tile((int)blockIdx.x + k * (int)gridDim.x, ntb, mbi, mbj);
#pragma unroll
            for (int a = 0; a < 2; a++)
#pragma unroll
                for (int b = 0; b < 4; b++)
#pragma unroll
                    for (int e = 0; e < 4; e++) acc[a][b][e] = 0.f;
        }

        mma_chunk_w(acc, sb + SM_STAGE + s * STAGE_SZ, m_base, n_base, lane);
        if (lane == 0) MBAR_ARRIVE(sb + SM_EMPTY + s * 8);

        // producer: refill this stage with chunk g+4 once all warps released it
        if (tid == 0 && g + 4 < G) {
            mbar_wait(sb + SM_EMPTY + s * 8, (uint32_t)(k & 1));
            FENCE_ASYNC();
            int lbi, lbj;
            decode_tile((int)blockIdx.x + (k + 1) * (int)gridDim.x, ntb, lbi, lbj);
            uint32_t fb = sb + SM_FULL + s * 8;
            MBAR_EXPECT_TX(fb, 2 * CHUNK_BYTES);
            uint32_t st = sb + SM_STAGE + s * STAGE_SZ;
            const char* A = (const char*)g_f16s + ((((size_t)(lbi >> 7)) * NCH + s) << 14);
            const char* B = (const char*)g_f16s + ((((size_t)(lbj >> 7)) * NCH + s) << 14);
            bulk_g2s(st, A, fb);
            bulk_g2s(st + CHUNK_BYTES, B, fb);
        }

        if (s == 3) {
            // ---- epilogue: d^2, row + column masked reductions (xx/lab via L2) ----
            float xi[4]; int li[4];
#pragma unroll
            for (int mt = 0; mt < 2; mt++)
#pragma unroll
                for (int rh = 0; rh < 2; rh++) {
                    int gi = mbi + m_base + mt * 16 + (lane >> 2) + 8 * rh;
                    xi[mt * 2 + rh] = __ldg(&g_xx[gi]);
                    li[mt * 2 + rh] = __ldg(&g_lab[gi]);
                }
            float xj[8]; int lj[8];
#pragma unroll
            for (int nt = 0; nt < 4; nt++)
#pragma unroll
                for (int cc = 0; cc < 2; cc++) {
                    int gj = mbj + n_base + nt * 8 + (lane & 3) * 2 + cc;
                    xj[nt * 2 + cc] = __ldg(&g_xx[gj]);
                    lj[nt * 2 + cc] = __ldg(&g_lab[gj]);
                }
#pragma unroll
            for (int mt = 0; mt < 2; mt++)
#pragma unroll
                for (int nt = 0; nt < 4; nt++)
#pragma unroll
                    for (int e = 0; e < 4; e++) {
                        int rh = e >> 1, cc = e & 1;
                        acc[mt][nt][e] = fmaf(-2.f, acc[mt][nt][e],
                                              xi[mt * 2 + rh] + xj[nt * 2 + cc]);
                    }

            // row direction: rows of block mbi vs cols of block mbj
#pragma unroll
            for (int mt = 0; mt < 2; mt++)
#pragma unroll
                for (int rh = 0; rh < 2; rh++) {
                    float pm = -1.f, nm = FLT_MAX;
                    const int L = li[mt * 2 + rh];
#pragma unroll
                    for (int nt = 0; nt < 4; nt++)
#pragma unroll
                        for (int cc = 0; cc < 2; cc++) {
                            float v = acc[mt][nt][rh * 2 + cc];
                            if (L == lj[nt * 2 + cc]) pm = fmaxf(pm, v);
                            else                      nm = fminf(nm, v);
                        }
                    pm = fmaxf(pm, __shfl_xor_sync(0xffffffffu, pm, 1));
                    pm = fmaxf(pm, __shfl_xor_sync(0xffffffffu, pm, 2));
                    nm = fminf(nm, __shfl_xor_sync(0xffffffffu, nm, 1));
                    nm = fminf(nm, __shfl_xor_sync(0xffffffffu, nm, 2));
                    if ((lane & 3) == 0) {
                        int gi = mbi + m_base + mt * 16 + (lane >> 2) + 8 * rh;
                        atomicMax(&g_posmax[gi], __float_as_int(pm));
                        atomicMin(&g_negmin[gi], __float_as_int(nm));
                    }
                }

            // column direction (symmetry): rows of block mbj vs cols of block mbi
#pragma unroll
            for (int nt = 0; nt < 4; nt++)
#pragma unroll
                for (int cc = 0; cc < 2; cc++) {
                    float pm = -1.f, nm = FLT_MAX;
                    const int L = lj[nt * 2 + cc];
#pragma unroll
                    for (int mt = 0; mt < 2; mt++)
#pragma unroll
                        for (int rh = 0; rh < 2; rh++) {
                            float v = acc[mt][nt][rh * 2 + cc];
                            if (L == li[mt * 2 + rh]) pm = fmaxf(pm, v);
                            else                      nm = fminf(nm, v);
                        }
                    pm = fmaxf(pm, __shfl_xor_sync(0xffffffffu, pm, 4));
                    pm = fmaxf(pm, __shfl_xor_sync(0xffffffffu, pm, 8));
                    pm = fmaxf(pm, __shfl_xor_sync(0xffffffffu, pm, 16));
                    nm = fminf(nm, __shfl_xor_sync(0xffffffffu, nm, 4));
                    nm = fminf(nm, __shfl_xor_sync(0xffffffffu, nm, 8));
                    nm = fminf(nm, __shfl_xor_sync(0xffffffffu, nm, 16));
                    if (lane < 4) {
                        int gj = mbj + n_base + nt * 8 + (lane & 3) * 2 + cc;
                        atomicMax(&g_posmax[gj], __float_as_int(pm));
                        atomicMin(&g_negmin[gj], __float_as_int(nm));
                    }
                }
        }
    }
}

// ---------------------------------------------------------------------------
// Finalize: sqrt, validity, margin ranking loss mean.
// ---------------------------------------------------------------------------
__global__ void finalize_kernel(float* __restrict__ out, int n) {
    __shared__ float ss[256];
    __shared__ float sc[256];
    float sum = 0.f, cnt = 0.f;
    for (int i = threadIdx.x; i < n; i += 256) {
        float ap2 = __int_as_float(g_posmax[i]);
        float ap  = sqrtf(fmaxf(ap2, 1e-12f));
        float nm2 = __int_as_float(g_negmin[i]);
        bool  has_neg = nm2 < 1e30f;
        float an  = has_neg ? sqrtf(fmaxf(nm2, 1e-12f)) : 0.f;
        bool  valid = (ap < 1000000.0f) && (an > 0.f);
        if (valid) {
            sum += fmaxf(0.3f + ap - an, 0.f);
            cnt += 1.f;
        }
    }
    ss[threadIdx.x] = sum;
    sc[threadIdx.x] = cnt;
    __syncthreads();
    for (int o = 128; o; o >>= 1) {
        if (threadIdx.x < o) {
            ss[threadIdx.x] += ss[threadIdx.x + o];
            sc[threadIdx.x] += sc[threadIdx.x + o];
        }
        __syncthreads();
    }
    if (threadIdx.x == 0)
        out[0] = (sc[0] > 0.f) ? ss[0] / fmaxf(sc[0], 1.f) : 0.f;
}

// ---------------------------------------------------------------------------
extern "C" void kernel_launch(void* const* d_in, const int* in_sizes, int n_in,
                              void* d_out, int out_size) {
    const float* feat   = (const float*)d_in[0];
    const int*   labels = (const int*)d_in[1];   // int32/int64 auto-detected
    int n = in_sizes[1];                         // 4096

    cudaFuncSetAttribute(tile_kernel, cudaFuncAttributeMaxDynamicSharedMemorySize,
                         SMEM_TOTAL);

    prep_kernel<<<(n + 7) / 8, 256>>>(feat, labels, n);
    tile_kernel<<<148, NTHR, SMEM_TOTAL>>>(n);
    finalize_kernel<<<1, 256>>>((float*)d_out, n);
}

// round 9
// speedup vs baseline: 2.6456x; 1.1941x over previous
#include <cuda_runtime.h>
#include <cuda_fp16.h>
#include <float.h>
#include <stdint.h>

#define NMAX 4096
#define DIMK 256              // fp32 features per row
#define NSC  4                // 16KB sub-chunks per 128-row block (64 cols each)
#define NBC  2                // big-chunks (128 cols) per tile
#define NSTG 3                // smem pipeline stages
#define NTHR 512
#define SUB_BYTES 16384       // one 128x64 fp16 sub-chunk, pre-swizzled

// ---------------- device scratch (no allocs allowed) ----------------
__device__ int   g_posmax[NMAX];                 // max d^2 over positives, float bits
__device__ int   g_negmin[NMAX];                 // min d^2 over negatives, float bits
__device__ float g_xx[NMAX];                     // squared norms (exact fp32)
__device__ int   g_lab[NMAX];                    // normalized labels
__device__ int   g_done;                         // CTA completion counter
// chunk-major pre-swizzled fp16 features:
// block b = row/128, sub-chunk c = col/64 -> contiguous 16KB at ((b*4+c)<<14)
__device__ __align__(16) __half g_f16s[NMAX * DIMK];

// ---------------- PTX helpers (sm_90-baseline ISA) ----------------
__device__ __forceinline__ uint32_t s2u(const void* p) {
    uint32_t a;
    asm("{ .reg .u64 t; cvta.to.shared.u64 t, %1; cvt.u32.u64 %0, t; }" : "=r"(a) : "l"(p));
    return a;
}
#define MBAR_INIT(a, c) asm volatile("mbarrier.init.shared.b64 [%0], %1;" :: "r"(a), "r"(c) : "memory")
#define MBAR_EXPECT_TX(a, b) asm volatile("mbarrier.arrive.expect_tx.shared.b64 _, [%0], %1;" :: "r"(a), "r"(b) : "memory")
#define MBAR_ARRIVE(a) asm volatile("mbarrier.arrive.release.cta.shared.b64 _, [%0];" :: "r"(a) : "memory")
#define FENCE_ASYNC()  asm volatile("fence.proxy.async.shared::cta;" ::: "memory")
__device__ __forceinline__ void mbar_wait(uint32_t mbar, uint32_t parity) {
    asm volatile(
        "{\n\t.reg .pred P;\n\t"
        "WL_%=:\n\t"
        "mbarrier.try_wait.parity.acquire.cta.shared::cta.b64 P, [%0], %1, 0x989680;\n\t"
        "@!P bra WL_%=;\n\t}"
        :: "r"(mbar), "r"(parity) : "memory");
}
__device__ __forceinline__ void bulk_g2s(uint32_t dst, const void* src, uint32_t mbar) {
    asm volatile(
        "cp.async.bulk.shared::cluster.global.mbarrier::complete_tx::bytes "
        "[%0], [%1], %2, [%3];"
        :: "r"(dst), "l"(src), "r"((uint32_t)SUB_BYTES), "r"(mbar) : "memory");
}
__device__ __forceinline__ void ldsm4(uint32_t* r, uint32_t a) {
    asm volatile("ldmatrix.sync.aligned.m8n8.x4.shared.b16 {%0,%1,%2,%3}, [%4];"
                 : "=r"(r[0]), "=r"(r[1]), "=r"(r[2]), "=r"(r[3]) : "r"(a));
}
__device__ __forceinline__ void mma16816(float* d, const uint32_t* a,
                                         uint32_t b0, uint32_t b1) {
    asm volatile(
        "mma.sync.aligned.m16n8k16.row.col.f32.f16.f16.f32 "
        "{%0,%1,%2,%3}, {%4,%5,%6,%7}, {%8,%9}, {%0,%1,%2,%3};"
        : "+f"(d[0]), "+f"(d[1]), "+f"(d[2]), "+f"(d[3])
        : "r"(a[0]), "r"(a[1]), "r"(a[2]), "r"(a[3]), "r"(b0), "r"(b1));
}
__device__ __forceinline__ float ldcg_f(const float* p) {
    float v; asm volatile("ld.global.cg.f32 %0, [%1];" : "=f"(v) : "l"(p)); return v;
}
__device__ __forceinline__ int ldcg_i(const int* p) {
    int v; asm volatile("ld.global.cg.s32 %0, [%1];" : "=r"(v) : "l"(p)); return v;
}
#define SWZ(x) ((x) ^ ((((uint32_t)(x)) >> 3) & 0x70))

// SMEM layout (relative to 1024-aligned base)
#define SM_FULL   0           // 3 x 8B mbarriers
#define SM_EMPTY  64          // 3 x 8B mbarriers
#define SM_FLAG   512         // finalize election flag
#define SM_STAGE  1024        // 3 stages x 64KB (A 32KB + B 32KB)
#define STAGE_SZ  65536
#define SMEM_TOTAL (SM_STAGE + NSTG * STAGE_SZ + 1024)

// ---------------------------------------------------------------------------
// Prep: fp16 convert into chunk-major PRE-SWIZZLED layout, exact fp32 norms,
// label normalization, reduction + counter init. One warp per row.
// ---------------------------------------------------------------------------
__global__ void prep_kernel(const float* __restrict__ feat,
                            const int* __restrict__ lab_raw, int n) {
    int row  = blockIdx.x * 8 + (threadIdx.x >> 5);
    int lane = threadIdx.x & 31;
    if (row >= n) return;

    const float4* p = (const float4*)(feat + (size_t)row * DIMK);
    float4 v0 = p[2 * lane];          // cols lane*8 .. lane*8+3
    float4 v1 = p[2 * lane + 1];      // cols lane*8+4 .. lane*8+7

    float s = v0.x * v0.x + v0.y * v0.y + v0.z * v0.z + v0.w * v0.w
            + v1.x * v1.x + v1.y * v1.y + v1.z * v1.z + v1.w * v1.w;

    __half2 h0 = __floats2half2_rn(v0.x, v0.y);
    __half2 h1 = __floats2half2_rn(v0.z, v0.w);
    __half2 h2 = __floats2half2_rn(v1.x, v1.y);
    __half2 h3 = __floats2half2_rn(v1.z, v1.w);
    uint4 pk;
    pk.x = *(uint32_t*)&h0; pk.y = *(uint32_t*)&h1;
    pk.z = *(uint32_t*)&h2; pk.w = *(uint32_t*)&h3;

    const int blk = row >> 7;                 // 128-row block
    const int c   = lane >> 3;                // sub-chunk = (lane*8)/64
    const uint32_t in_off = SWZ(((uint32_t)(row & 127)) * 128 + (lane & 7) * 16);
    char* dst = (char*)g_f16s + (((size_t)blk * NSC + c) << 14) + in_off;
    *(uint4*)dst = pk;

#pragma unroll
    for (int o = 16; o; o >>= 1) s += __shfl_xor_sync(0xffffffffu, s, o);

    if (lane == 0) {
        g_xx[row]     = s;
        g_posmax[row] = 0;                       // bits of +0.0f
        g_negmin[row] = __float_as_int(FLT_MAX);
    }
    if (lane == 1) {
        bool is64 = true;
#pragma unroll
        for (int i = 0; i < 32; i++)
            if (lab_raw[2 * i + 1] != 0) { is64 = false; break; }
        g_lab[row] = is64 ? lab_raw[2 * row] : lab_raw[row];
    }
    if (row == 0 && lane == 2) g_done = 0;
}

// ---------------------------------------------------------------------------
__device__ __forceinline__ void decode_tile(int t, int ntb, int& bi, int& bj) {
    int ti = 0;
    while (t >= ntb - ti) { t -= ntb - ti; ti++; }
    bi = ti << 7;
    bj = (ti + t) << 7;
}

// Issue the 4 bulk copies for one big-chunk (A 2 sub-chunks + B 2 sub-chunks)
__device__ __forceinline__ void issue_bigchunk(uint32_t st, uint32_t fb,
                                               int bi, int bj, int c2) {
    MBAR_EXPECT_TX(fb, 4 * SUB_BYTES);
    const char* A = (const char*)g_f16s + ((((size_t)(bi >> 7)) * NSC + c2 * 2) << 14);
    const char* B = (const char*)g_f16s + ((((size_t)(bj >> 7)) * NSC + c2 * 2) << 14);
    bulk_g2s(st,                 A,             fb);
    bulk_g2s(st + SUB_BYTES,     A + SUB_BYTES, fb);
    bulk_g2s(st + 2 * SUB_BYTES, B,             fb);
    bulk_g2s(st + 3 * SUB_BYTES, B + SUB_BYTES, fb);
}

// MMA over one 128-col big-chunk, per-warp 32x32 output (fp16 single product).
__device__ __forceinline__ void mma_bigchunk(float acc[2][4][4], uint32_t st,
                                             int m_base, int n_base, int lane) {
#pragma unroll
    for (int s8 = 0; s8 < 8; s8++) {              // k16 steps within 128 cols
        const int sc = s8 >> 2, ks = s8 & 3;
        const uint32_t sA = st + sc * SUB_BYTES;
        const uint32_t sB = st + 2 * SUB_BYTES + sc * SUB_BYTES;
        const uint32_t koff = (uint32_t)ks * 32 + ((lane >> 4) << 4);
        uint32_t a[2][4], b[2][4];
#pragma unroll
        for (int mt = 0; mt < 2; mt++) {
            uint32_t ad = SWZ((uint32_t)(m_base + mt * 16 + (lane & 15)) * 128 + koff);
            ldsm4(a[mt], sA + ad);
        }
#pragma unroll
        for (int p = 0; p < 2; p++) {
            uint32_t bd = SWZ((uint32_t)(n_base + p * 16 + (lane & 15)) * 128 + koff);
            ldsm4(b[p], sB + bd);
        }
#pragma unroll
        for (int mt = 0; mt < 2; mt++)
#pragma unroll
            for (int nt = 0; nt < 4; nt++) {
                const int p = nt >> 1, q = nt & 1;
                mma16816(acc[mt][nt], a[mt], b[p][q], b[p][2 + q]);
            }
    }
}

// ---------------------------------------------------------------------------
// Persistent kernel: bulk-copy producer + 3-stage 64KB mbarrier ring,
// 16 warps (4x4, 32x32 each), prefetched dual-direction epilogue,
// last CTA folds in the finalize reduction.
// ---------------------------------------------------------------------------
__global__ void __launch_bounds__(NTHR, 1) tile_kernel(float* __restrict__ out, int n) {
    extern __shared__ char smem_raw[];
    uint32_t sb_raw = s2u(smem_raw);
    uint32_t pad = (1024u - (sb_raw & 1023u)) & 1023u;
    char* sm = smem_raw + pad;
    uint32_t sb = sb_raw + pad;

    const int tid = threadIdx.x, lane = tid & 31, w = tid >> 5;
    const int m_base = (w & 3) * 32;     // 4 warps along M
    const int n_base = (w >> 2) * 32;    // 4 warps along N

    const int ntb = n >> 7;
    const int T   = ntb * (ntb + 1) / 2;          // upper triangle incl. diagonal
    const int myT = (T - (int)blockIdx.x + (int)gridDim.x - 1) / (int)gridDim.x;
    const int G   = myT * NBC;                    // big-chunks this CTA streams

    if (tid == 0) {
#pragma unroll
        for (int s = 0; s < NSTG; s++) {
            MBAR_INIT(sb + SM_FULL + s * 8, 1);
            MBAR_INIT(sb + SM_EMPTY + s * 8, 16);
        }
    }
    __syncthreads();

    if (G > 0) {
        // prologue: issue big-chunks 0..2
        if (tid == 0) {
#pragma unroll
            for (int c = 0; c < NSTG; c++) {
                if (c < G) {
                    int bi0, bj0;
                    decode_tile((int)blockIdx.x + (c >> 1) * (int)gridDim.x, ntb, bi0, bj0);
                    issue_bigchunk(sb + SM_STAGE + c * STAGE_SZ,
                                   sb + SM_FULL + c * 8, bi0, bj0, c & 1);
                }
            }
        }

        float acc[2][4][4];
        float xi[4], xj[8];
        int   li[4], lj[8];
        int   mbi = 0, mbj = 0;
        int   stg = 0;
        uint32_t par = 0;

        for (int g = 0; g < G; g++) {
            mbar_wait(sb + SM_FULL + stg * 8, par);

            if ((g & 1) == 0) {
                decode_tile((int)blockIdx.x + (g >> 1) * (int)gridDim.x, ntb, mbi, mbj);
#pragma unroll
                for (int a = 0; a < 2; a++)
#pragma unroll
                    for (int b = 0; b < 4; b++)
#pragma unroll
                        for (int e = 0; e < 4; e++) acc[a][b][e] = 0.f;
                // prefetch epilogue operands (overlaps this tile's MMAs)
#pragma unroll
                for (int mt = 0; mt < 2; mt++)
#pragma unroll
                    for (int rh = 0; rh < 2; rh++) {
                        int gi = mbi + m_base + mt * 16 + (lane >> 2) + 8 * rh;
                        xi[mt * 2 + rh] = __ldg(&g_xx[gi]);
                        li[mt * 2 + rh] = __ldg(&g_lab[gi]);
                    }
#pragma unroll
                for (int nt = 0; nt < 4; nt++)
#pragma unroll
                    for (int cc = 0; cc < 2; cc++) {
                        int gj = mbj + n_base + nt * 8 + (lane & 3) * 2 + cc;
                        xj[nt * 2 + cc] = __ldg(&g_xx[gj]);
                        lj[nt * 2 + cc] = __ldg(&g_lab[gj]);
                    }
            }

            mma_bigchunk(acc, sb + SM_STAGE + stg * STAGE_SZ, m_base, n_base, lane);
            if (lane == 0) MBAR_ARRIVE(sb + SM_EMPTY + stg * 8);

            // producer: refill this stage with big-chunk g+3
            if (tid == 0 && g + NSTG < G) {
                mbar_wait(sb + SM_EMPTY + stg * 8, par);
                FENCE_ASYNC();
                int lbi, lbj;
                const int cl = g + NSTG;
                decode_tile((int)blockIdx.x + (cl >> 1) * (int)gridDim.x, ntb, lbi, lbj);
                issue_bigchunk(sb + SM_STAGE + stg * STAGE_SZ,
                               sb + SM_FULL + stg * 8, lbi, lbj, cl & 1);
            }

            if ((g & 1) == 1) {
                // ---- epilogue: d^2, row + column masked reductions ----
#pragma unroll
                for (int mt = 0; mt < 2; mt++)
#pragma unroll
                    for (int nt = 0; nt < 4; nt++)
#pragma unroll
                        for (int e = 0; e < 4; e++) {
                            int rh = e >> 1, cc = e & 1;
                            acc[mt][nt][e] = fmaf(-2.f, acc[mt][nt][e],
                                                  xi[mt * 2 + rh] + xj[nt * 2 + cc]);
                        }

                // row direction: rows of block mbi vs cols of block mbj
#pragma unroll
                for (int mt = 0; mt < 2; mt++)
#pragma unroll
                    for (int rh = 0; rh < 2; rh++) {
                        float pm = -1.f, nm = FLT_MAX;
                        const int L = li[mt * 2 + rh];
#pragma unroll
                        for (int nt = 0; nt < 4; nt++)
#pragma unroll
                            for (int cc = 0; cc < 2; cc++) {
                                float v = acc[mt][nt][rh * 2 + cc];
                                if (L == lj[nt * 2 + cc]) pm = fmaxf(pm, v);
                                else                      nm = fminf(nm, v);
                            }
                        pm = fmaxf(pm, __shfl_xor_sync(0xffffffffu, pm, 1));
                        pm = fmaxf(pm, __shfl_xor_sync(0xffffffffu, pm, 2));
                        nm = fminf(nm, __shfl_xor_sync(0xffffffffu, nm, 1));
                        nm = fminf(nm, __shfl_xor_sync(0xffffffffu, nm, 2));
                        if ((lane & 3) == 0) {
                            int gi = mbi + m_base + mt * 16 + (lane >> 2) + 8 * rh;
                            atomicMax(&g_posmax[gi], __float_as_int(pm));
                            atomicMin(&g_negmin[gi], __float_as_int(nm));
                        }
                    }

                // column direction (symmetry): rows of block mbj vs cols of mbi
#pragma unroll
                for (int nt = 0; nt < 4; nt++)
#pragma unroll
                    for (int cc = 0; cc < 2; cc++) {
                        float pm = -1.f, nm = FLT_MAX;
                        const int L = lj[nt * 2 + cc];
#pragma unroll
                        for (int mt = 0; mt < 2; mt++)
#pragma unroll
                            for (int rh = 0; rh < 2; rh++) {
                                float v = acc[mt][nt][rh * 2 + cc];
                                if (L == li[mt * 2 + rh]) pm = fmaxf(pm, v);
                                else                      nm = fminf(nm, v);
                            }
                        pm = fmaxf(pm, __shfl_xor_sync(0xffffffffu, pm, 4));
                        pm = fmaxf(pm, __shfl_xor_sync(0xffffffffu, pm, 8));
                        pm = fmaxf(pm, __shfl_xor_sync(0xffffffffu, pm, 16));
                        nm = fminf(nm, __shfl_xor_sync(0xffffffffu, nm, 4));
                        nm = fminf(nm, __shfl_xor_sync(0xffffffffu, nm, 8));
                        nm = fminf(nm, __shfl_xor_sync(0xffffffffu, nm, 16));
                        if (lane < 4) {
                            int gj = mbj + n_base + nt * 8 + (lane & 3) * 2 + cc;
                            atomicMax(&g_posmax[gj], __float_as_int(pm));
                            atomicMin(&g_negmin[gj], __float_as_int(nm));
                        }
                    }
            }

            if (++stg == NSTG) { stg = 0; par ^= 1; }
        }
    }

    // ---- completion counter: last CTA performs the finalize reduction ----
    __syncthreads();
    if (tid == 0) {
        __threadfence();
        int prev = atomicAdd(&g_done, 1);
        *(volatile int*)(sm + SM_FLAG) = (prev == (int)gridDim.x - 1) ? 1 : 0;
    }
    __syncthreads();
    if (*(volatile int*)(sm + SM_FLAG)) {
        float* ss = (float*)(sm + SM_STAGE);
        float* sc = ss + NTHR;
        float sum = 0.f, cnt = 0.f;
        for (int i = tid; i < n; i += NTHR) {
            float ap2 = __int_as_float(ldcg_i(&g_posmax[i]));
            float ap  = sqrtf(fmaxf(ap2, 1e-12f));
            float nm2 = __int_as_float(ldcg_i(&g_negmin[i]));
            bool  has_neg = nm2 < 1e30f;
            float an  = has_neg ? sqrtf(fmaxf(nm2, 1e-12f)) : 0.f;
            bool  valid = (ap < 1000000.0f) && (an > 0.f);
            if (valid) {
                sum += fmaxf(0.3f + ap - an, 0.f);
                cnt += 1.f;
            }
        }
        ss[tid] = sum;
        sc[tid] = cnt;
        __syncthreads();
        for (int o = NTHR / 2; o; o >>= 1) {
            if (tid < o) {
                ss[tid] += ss[tid + o];
                sc[tid] += sc[tid + o];
            }
            __syncthreads();
        }
        if (tid == 0)
            out[0] = (sc[0] > 0.f) ? ss[0] / fmaxf(sc[0], 1.f) : 0.f;
    }
}

// ---------------------------------------------------------------------------
extern "C" void kernel_launch(void* const* d_in, const int* in_sizes, int n_in,
                              void* d_out, int out_size) {
    const float* feat   = (const float*)d_in[0];
    const int*   labels = (const int*)d_in[1];   // int32/int64 auto-detected
    int n = in_sizes[1];                         // 4096

    cudaFuncSetAttribute(tile_kernel, cudaFuncAttributeMaxDynamicSharedMemorySize,
                         SMEM_TOTAL);

    prep_kernel<<<(n + 7) / 8, 256>>>(feat, labels, n);
    tile_kernel<<<148, NTHR, SMEM_TOTAL>>>((float*)d_out, n);
}

// round 10
// speedup vs baseline: 2.8041x; 1.0599x over previous
#include <cuda_runtime.h>
#include <cuda_fp16.h>
#include <float.h>
#include <stdint.h>

#define NMAX 4096
#define DIMK 256              // fp32 features per row
#define NSC  4                // 16KB sub-chunks per 128-row block (64 cols each)
#define NSTG 2                // smem pipeline stages
#define NTHR 512
#define SUB_BYTES   16384
#define BLOCK_BYTES 32768     // 128 rows x 128 kcols (2 contiguous sub-chunks)

// ---------------- device scratch (no allocs allowed) ----------------
__device__ int   g_posmax[NMAX];                 // max d^2 over positives, float bits
__device__ int   g_negmin[NMAX];                 // min d^2 over negatives, float bits
__device__ float g_xx[NMAX];                     // squared norms (exact fp32)
__device__ int   g_lab[NMAX];                    // normalized labels
__device__ int   g_done;                         // CTA completion counter
// chunk-major pre-swizzled fp16 features:
// block b = row/128, sub-chunk c = col/64 -> contiguous 16KB at ((b*4+c)<<14)
__device__ __align__(16) __half g_f16s[NMAX * DIMK];

// ---------------- PTX helpers (sm_90-baseline ISA) ----------------
__device__ __forceinline__ uint32_t s2u(const void* p) {
    uint32_t a;
    asm("{ .reg .u64 t; cvta.to.shared.u64 t, %1; cvt.u32.u64 %0, t; }" : "=r"(a) : "l"(p));
    return a;
}
#define MBAR_INIT(a, c) asm volatile("mbarrier.init.shared.b64 [%0], %1;" :: "r"(a), "r"(c) : "memory")
#define MBAR_EXPECT_TX(a, b) asm volatile("mbarrier.arrive.expect_tx.shared.b64 _, [%0], %1;" :: "r"(a), "r"(b) : "memory")
#define MBAR_ARRIVE(a) asm volatile("mbarrier.arrive.release.cta.shared.b64 _, [%0];" :: "r"(a) : "memory")
#define FENCE_ASYNC()  asm volatile("fence.proxy.async.shared::cta;" ::: "memory")
__device__ __forceinline__ void mbar_wait(uint32_t mbar, uint32_t parity) {
    asm volatile(
        "{\n\t.reg .pred P;\n\t"
        "WL_%=:\n\t"
        "mbarrier.try_wait.parity.acquire.cta.shared::cta.b64 P, [%0], %1, 0x989680;\n\t"
        "@!P bra WL_%=;\n\t}"
        :: "r"(mbar), "r"(parity) : "memory");
}
__device__ __forceinline__ void bulk_g2s(uint32_t dst, const void* src, uint32_t mbar) {
    asm volatile(
        "cp.async.bulk.shared::cluster.global.mbarrier::complete_tx::bytes "
        "[%0], [%1], %2, [%3];"
        :: "r"(dst), "l"(src), "r"((uint32_t)BLOCK_BYTES), "r"(mbar) : "memory");
}
__device__ __forceinline__ void ldsm4(uint32_t* r, uint32_t a) {
    asm volatile("ldmatrix.sync.aligned.m8n8.x4.shared.b16 {%0,%1,%2,%3}, [%4];"
                 : "=r"(r[0]), "=r"(r[1]), "=r"(r[2]), "=r"(r[3]) : "r"(a));
}
__device__ __forceinline__ void mma16816(float* d, const uint32_t* a,
                                         uint32_t b0, uint32_t b1) {
    asm volatile(
        "mma.sync.aligned.m16n8k16.row.col.f32.f16.f16.f32 "
        "{%0,%1,%2,%3}, {%4,%5,%6,%7}, {%8,%9}, {%0,%1,%2,%3};"
        : "+f"(d[0]), "+f"(d[1]), "+f"(d[2]), "+f"(d[3])
        : "r"(a[0]), "r"(a[1]), "r"(a[2]), "r"(a[3]), "r"(b0), "r"(b1));
}
__device__ __forceinline__ int ldcg_i(const int* p) {
    int v; asm volatile("ld.global.cg.s32 %0, [%1];" : "=r"(v) : "l"(p)); return v;
}
#define SWZ(x) ((x) ^ ((((uint32_t)(x)) >> 3) & 0x70))

// SMEM layout (relative to 1024-aligned base)
#define SM_FULL   0           // 2 x 8B mbarriers
#define SM_EMPTY  64          // 2 x 8B mbarriers
#define SM_FLAG   128
#define SM_XXI    256         // 128 float
#define SM_LABI   768         // 128 int
#define SM_XXJ    1280        // 256 float
#define SM_LABJ   2304        // 256 int
#define SM_STAGE  4096        // 2 stages x 96KB: A(32K) | B0(32K) | B1(32K)
#define STAGE_SZ  98304
#define SMEM_TOTAL (SM_STAGE + NSTG * STAGE_SZ + 1024)

// ---------------------------------------------------------------------------
// Prep: fp16 convert into chunk-major PRE-SWIZZLED layout, exact fp32 norms,
// label normalization, reduction + counter init. One warp per row.
// ---------------------------------------------------------------------------
__global__ void prep_kernel(const float* __restrict__ feat,
                            const int* __restrict__ lab_raw, int n) {
    int row  = blockIdx.x * 8 + (threadIdx.x >> 5);
    int lane = threadIdx.x & 31;
    if (row >= n) return;

    const float4* p = (const float4*)(feat + (size_t)row * DIMK);
    float4 v0 = p[2 * lane];
    float4 v1 = p[2 * lane + 1];

    float s = v0.x * v0.x + v0.y * v0.y + v0.z * v0.z + v0.w * v0.w
            + v1.x * v1.x + v1.y * v1.y + v1.z * v1.z + v1.w * v1.w;

    __half2 h0 = __floats2half2_rn(v0.x, v0.y);
    __half2 h1 = __floats2half2_rn(v0.z, v0.w);
    __half2 h2 = __floats2half2_rn(v1.x, v1.y);
    __half2 h3 = __floats2half2_rn(v1.z, v1.w);
    uint4 pk;
    pk.x = *(uint32_t*)&h0; pk.y = *(uint32_t*)&h1;
    pk.z = *(uint32_t*)&h2; pk.w = *(uint32_t*)&h3;

    const int blk = row >> 7;
    const int c   = lane >> 3;
    const uint32_t in_off = SWZ(((uint32_t)(row & 127)) * 128 + (lane & 7) * 16);
    char* dst = (char*)g_f16s + (((size_t)blk * NSC + c) << 14) + in_off;
    *(uint4*)dst = pk;

#pragma unroll
    for (int o = 16; o; o >>= 1) s += __shfl_xor_sync(0xffffffffu, s, o);

    if (lane == 0) {
        g_xx[row]     = s;
        g_posmax[row] = 0;
        g_negmin[row] = __float_as_int(FLT_MAX);
    }
    if (lane == 1) {
        bool is64 = true;
#pragma unroll
        for (int i = 0; i < 32; i++)
            if (lab_raw[2 * i + 1] != 0) { is64 = false; break; }
        g_lab[row] = is64 ? lab_raw[2 * row] : lab_raw[row];
    }
    if (row == 0 && lane == 2) g_done = 0;
}

// ---------------------------------------------------------------------------
// Supertile enumeration: (ti, sj) with j-superblock sj covering blocks
// {2sj, 2sj+1}, kept if 2sj+1 >= ti. (Transpose-duplicate halves are harmless:
// max/min reductions are idempotent.)  Count = 272 for ntb=32.
// ---------------------------------------------------------------------------
__device__ __forceinline__ void decode_st(int t, int nsb, int& ti, int& sj) {
    ti = 0;
    while (t >= nsb - (ti >> 1)) { t -= nsb - (ti >> 1); ti++; }
    sj = (ti >> 1) + t;
}

// Refill one big-chunk (128 kcols): A + B0 + B1, three 32KB bulk copies.
__device__ __forceinline__ void issue_bigchunk(uint32_t st, uint32_t fb,
                                               int ti, int sj, int c2) {
    MBAR_EXPECT_TX(fb, 3 * BLOCK_BYTES);
    const char* A  = (const char*)g_f16s + ((((size_t)ti)       * NSC + c2 * 2) << 14);
    const char* B0 = (const char*)g_f16s + ((((size_t)(2 * sj))     * NSC + c2 * 2) << 14);
    const char* B1 = (const char*)g_f16s + ((((size_t)(2 * sj + 1)) * NSC + c2 * 2) << 14);
    bulk_g2s(st,                   A,  fb);
    bulk_g2s(st + BLOCK_BYTES,     B0, fb);
    bulk_g2s(st + 2 * BLOCK_BYTES, B1, fb);
}

// MMA over one 128-kcol big-chunk, per-warp 32x64 output.
__device__ __forceinline__ void mma_bigchunk(float acc[2][8][4], uint32_t st,
                                             int m_base, int n_base, int lane) {
    const uint32_t sA = st;
    const uint32_t sB = st + BLOCK_BYTES + ((uint32_t)(n_base >> 7)) * BLOCK_BYTES;
    const int nloc = n_base & 64;
#pragma unroll
    for (int s8 = 0; s8 < 8; s8++) {
        const int sc = s8 >> 2, ks = s8 & 3;
        const uint32_t so = (uint32_t)sc * SUB_BYTES;
        const uint32_t koff = (uint32_t)ks * 32 + ((lane >> 4) << 4);
        uint32_t a[2][4], b[4][4];
#pragma unroll
        for (int mt = 0; mt < 2; mt++) {
            uint32_t ad = SWZ((uint32_t)(m_base + mt * 16 + (lane & 15)) * 128 + koff);
            ldsm4(a[mt], sA + so + ad);
        }
#pragma unroll
        for (int p = 0; p < 4; p++) {
            uint32_t bd = SWZ((uint32_t)(nloc + p * 16 + (lane & 15)) * 128 + koff);
            ldsm4(b[p], sB + so + bd);
        }
#pragma unroll
        for (int mt = 0; mt < 2; mt++)
#pragma unroll
            for (int nt = 0; nt < 8; nt++) {
                const int p = nt >> 1, q = nt & 1;
                mma16816(acc[mt][nt], a[mt], b[p][q], b[p][2 + q]);
            }
    }
}

// ---------------------------------------------------------------------------
// Persistent kernel: 128x256 supertiles, 2-stage 96KB ring, early producer,
// smem-staged epilogue operands, fused final reduction.
// ---------------------------------------------------------------------------
__global__ void __launch_bounds__(NTHR, 1) tile_kernel(float* __restrict__ out, int n) {
    extern __shared__ char smem_raw[];
    uint32_t sb_raw = s2u(smem_raw);
    uint32_t pad = (1024u - (sb_raw & 1023u)) & 1023u;
    char* sm = smem_raw + pad;
    uint32_t sb = sb_raw + pad;

    float* xxi_s  = (float*)(sm + SM_XXI);
    int*   labi_s = (int*)(sm + SM_LABI);
    float* xxj_s  = (float*)(sm + SM_XXJ);
    int*   labj_s = (int*)(sm + SM_LABJ);

    const int tid = threadIdx.x, lane = tid & 31, w = tid >> 5;
    const int m_base = (w & 3) * 32;     // 4 warps along M (128 rows)
    const int n_base = (w >> 2) * 64;    // 4 warps along N (256 cols)

    const int ntb = n >> 7;
    const int nsb = ntb >> 1;                     // j-superblocks
    // total supertiles
    int ST = 0;
    for (int t2 = 0; t2 < ntb; t2++) ST += nsb - (t2 >> 1);
    const int myST = (ST - (int)blockIdx.x + (int)gridDim.x - 1) / (int)gridDim.x;
    const int G    = myST * 2;                    // big-chunks this CTA streams

    if (tid == 0) {
#pragma unroll
        for (int s = 0; s < NSTG; s++) {
            MBAR_INIT(sb + SM_FULL + s * 8, 1);
            MBAR_INIT(sb + SM_EMPTY + s * 8, 16);
        }
    }
    __syncthreads();

    if (G > 0) {
        int ti0, sj0;
        decode_st(blockIdx.x, nsb, ti0, sj0);
        if (tid == 0) {
            issue_bigchunk(sb + SM_STAGE,            sb + SM_FULL,     ti0, sj0, 0);
            issue_bigchunk(sb + SM_STAGE + STAGE_SZ, sb + SM_FULL + 8, ti0, sj0, 1);
        }

        float acc[2][8][4];
        int ti = ti0, sj = sj0;

        for (int g = 0; g < G; g++) {
            const int s = g & 1;

            if ((g & 1) == 0) {
                // new supertile: decode + stage epilogue operands in smem
                if (g > 0) decode_st((int)blockIdx.x + (g >> 1) * (int)gridDim.x,
                                     nsb, ti, sj);
                __syncthreads();                   // prev epilogue done reading
                if (tid < 128) {
                    xxi_s[tid]  = g_xx[ti * 128 + tid];
                    labi_s[tid] = g_lab[ti * 128 + tid];
                } else if (tid < 384) {
                    int q = tid - 128;
                    xxj_s[q]  = g_xx[sj * 256 + q];
                    labj_s[q] = g_lab[sj * 256 + q];
                }
                __syncthreads();
#pragma unroll
                for (int a = 0; a < 2; a++)
#pragma unroll
                    for (int b = 0; b < 8; b++)
#pragma unroll
                        for (int e = 0; e < 4; e++) acc[a][b][e] = 0.f;
            }

            // early producer: refill the OTHER stage (released at chunk g-1)
            if (tid == 0 && g >= 1 && g + 1 < G) {
                uint32_t ep = (uint32_t)((((g + 1) >> 1) - 1) & 1);
                mbar_wait(sb + SM_EMPTY + (s ^ 1) * 8, ep);
                FENCE_ASYNC();
                int lti, lsj;
                decode_st((int)blockIdx.x + ((g + 1) >> 1) * (int)gridDim.x,
                          nsb, lti, lsj);
                issue_bigchunk(sb + SM_STAGE + (s ^ 1) * STAGE_SZ,
                               sb + SM_FULL + (s ^ 1) * 8, lti, lsj, (g + 1) & 1);
            }

            mbar_wait(sb + SM_FULL + s * 8, (uint32_t)((g >> 1) & 1));
            mma_bigchunk(acc, sb + SM_STAGE + s * STAGE_SZ, m_base, n_base, lane);
            if (lane == 0) MBAR_ARRIVE(sb + SM_EMPTY + s * 8);

            if ((g & 1) == 1) {
                // ---- epilogue over this warp's 32x64 block ----
                float xi[4]; int li[4];
#pragma unroll
                for (int mt = 0; mt < 2; mt++)
#pragma unroll
                    for (int rh = 0; rh < 2; rh++) {
                        int r = m_base + mt * 16 + (lane >> 2) + 8 * rh;
                        xi[mt * 2 + rh] = xxi_s[r];
                        li[mt * 2 + rh] = labi_s[r];
                    }
                float xj[16]; int lj[16];
#pragma unroll
                for (int nt = 0; nt < 8; nt++)
#pragma unroll
                    for (int cc = 0; cc < 2; cc++) {
                        int q = n_base + nt * 8 + (lane & 3) * 2 + cc;
                        xj[nt * 2 + cc] = xxj_s[q];
                        lj[nt * 2 + cc] = labj_s[q];
                    }
#pragma unroll
                for (int mt = 0; mt < 2; mt++)
#pragma unroll
                    for (int nt = 0; nt < 8; nt++)
#pragma unroll
                        for (int e = 0; e < 4; e++) {
                            int rh = e >> 1, cc = e & 1;
                            acc[mt][nt][e] = fmaf(-2.f, acc[mt][nt][e],
                                                  xi[mt * 2 + rh] + xj[nt * 2 + cc]);
                        }

                // row direction
#pragma unroll
                for (int mt = 0; mt < 2; mt++)
#pragma unroll
                    for (int rh = 0; rh < 2; rh++) {
                        float pm = -1.f, nm = FLT_MAX;
                        const int L = li[mt * 2 + rh];
#pragma unroll
                        for (int nt = 0; nt < 8; nt++)
#pragma unroll
                            for (int cc = 0; cc < 2; cc++) {
                                float v = acc[mt][nt][rh * 2 + cc];
                                if (L == lj[nt * 2 + cc]) pm = fmaxf(pm, v);
                                else                      nm = fminf(nm, v);
                            }
                        pm = fmaxf(pm, __shfl_xor_sync(0xffffffffu, pm, 1));
                        pm = fmaxf(pm, __shfl_xor_sync(0xffffffffu, pm, 2));
                        nm = fminf(nm, __shfl_xor_sync(0xffffffffu, nm, 1));
                        nm = fminf(nm, __shfl_xor_sync(0xffffffffu, nm, 2));
                        if ((lane & 3) == 0) {
                            int gi = ti * 128 + m_base + mt * 16 + (lane >> 2) + 8 * rh;
                            atomicMax(&g_posmax[gi], __float_as_int(pm));
                            atomicMin(&g_negmin[gi], __float_as_int(nm));
                        }
                    }

                // column direction (symmetry)
#pragma unroll
                for (int nt = 0; nt < 8; nt++)
#pragma unroll
                    for (int cc = 0; cc < 2; cc++) {
                        float pm = -1.f, nm = FLT_MAX;
                        const int L = lj[nt * 2 + cc];
#pragma unroll
                        for (int mt = 0; mt < 2; mt++)
#pragma unroll
                            for (int rh = 0; rh < 2; rh++) {
                                float v = acc[mt][nt][rh * 2 + cc];
                                if (L == li[mt * 2 + rh]) pm = fmaxf(pm, v);
                                else                      nm = fminf(nm, v);
                            }
                        pm = fmaxf(pm, __shfl_xor_sync(0xffffffffu, pm, 4));
                        pm = fmaxf(pm, __shfl_xor_sync(0xffffffffu, pm, 8));
                        pm = fmaxf(pm, __shfl_xor_sync(0xffffffffu, pm, 16));
                        nm = fminf(nm, __shfl_xor_sync(0xffffffffu, nm, 4));
                        nm = fminf(nm, __shfl_xor_sync(0xffffffffu, nm, 8));
                        nm = fminf(nm, __shfl_xor_sync(0xffffffffu, nm, 16));
                        if (lane < 4) {
                            int gj = sj * 256 + n_base + nt * 8 + (lane & 3) * 2 + cc;
                            atomicMax(&g_posmax[gj], __float_as_int(pm));
                            atomicMin(&g_negmin[gj], __float_as_int(nm));
                        }
                    }
            }
        }
    }

    // ---- completion counter: last CTA performs the finalize reduction ----
    __syncthreads();
    if (tid == 0) {
        __threadfence();
        int prev = atomicAdd(&g_done, 1);
        *(volatile int*)(sm + SM_FLAG) = (prev == (int)gridDim.x - 1) ? 1 : 0;
    }
    __syncthreads();
    if (*(volatile int*)(sm + SM_FLAG)) {
        float* ss = (float*)(sm + SM_STAGE);
        float* sc = ss + NTHR;
        float sum = 0.f, cnt = 0.f;
        for (int i = tid; i < n; i += NTHR) {
            float ap2 = __int_as_float(ldcg_i(&g_posmax[i]));
            float ap  = sqrtf(fmaxf(ap2, 1e-12f));
            float nm2 = __int_as_float(ldcg_i(&g_negmin[i]));
            bool  has_neg = nm2 < 1e30f;
            float an  = has_neg ? sqrtf(fmaxf(nm2, 1e-12f)) : 0.f;
            bool  valid = (ap < 1000000.0f) && (an > 0.f);
            if (valid) {
                sum += fmaxf(0.3f + ap - an, 0.f);
                cnt += 1.f;
            }
        }
        ss[tid] = sum;
        sc[tid] = cnt;
        __syncthreads();
        for (int o = NTHR / 2; o; o >>= 1) {
            if (tid < o) {
                ss[tid] += ss[tid + o];
                sc[tid] += sc[tid + o];
            }
            __syncthreads();
        }
        if (tid == 0)
            out[0] = (sc[0] > 0.f) ? ss[0] / fmaxf(sc[0], 1.f) : 0.f;
    }
}

// ---------------------------------------------------------------------------
extern "C" void kernel_launch(void* const* d_in, const int* in_sizes, int n_in,
                              void* d_out, int out_size) {
    const float* feat   = (const float*)d_in[0];
    const int*   labels = (const int*)d_in[1];   // int32/int64 auto-detected
    int n = in_sizes[1];                         // 4096

    cudaFuncSetAttribute(tile_kernel, cudaFuncAttributeMaxDynamicSharedMemorySize,
                         SMEM_TOTAL);

    prep_kernel<<<(n + 7) / 8, 256>>>(feat, labels, n);
    tile_kernel<<<148, NTHR, SMEM_TOTAL>>>((float*)d_out, n);
}